// round 1
// baseline (speedup 1.0000x reference)
#include <cuda_runtime.h>
#include <math.h>

#define Bc 512
#define Mc 4096
#define Nc 64
#define Kc 64
#define Hc 8
#define DKc 32
#define DVc 4
#define KERc 3
#define Ec 256   /* H*DK */
#define Fc 512   /* H*K  */
#define DOUTc 64

// Scratch (allocation-free rule: device globals)
__device__ float g_q[(size_t)Bc * Hc * Nc * DKc];   // 32 MB  q projected, (b,h,n,d)
__device__ float g_o[(size_t)Bc * Nc * Fc];         // 64 MB  attn@v,     (b,n, h*64+p)

// ---------------------------------------------------------------------------
// Kernel 1: per-batch LayerNorm + Q projection  q[b,n,e] = sum_k y[n*64+k]*Wq[e,k]
// grid = B, block = 256
// smem: y[4096] + Wq[256][65]
// ---------------------------------------------------------------------------
static constexpr int SMEM1 = (4096 + 256 * 65) * 4;

__global__ __launch_bounds__(256) void ln_q_kernel(
    const float* __restrict__ feat, const float* __restrict__ gamma,
    const float* __restrict__ beta, const float* __restrict__ Wq)
{
    extern __shared__ float sm[];
    float* s_y  = sm;            // 4096
    float* s_wq = sm + 4096;     // 256*65
    __shared__ float s_red[20];

    const int b = blockIdx.x, tid = threadIdx.x;
    const float* x = feat + (size_t)b * Mc;

    float sum = 0.f, sq = 0.f;
    for (int i = tid; i < Mc; i += 256) {
        float v = x[i];
        s_y[i] = v; sum += v; sq += v * v;
    }
    #pragma unroll
    for (int o = 16; o; o >>= 1) {
        sum += __shfl_xor_sync(~0u, sum, o);
        sq  += __shfl_xor_sync(~0u, sq,  o);
    }
    if ((tid & 31) == 0) { s_red[tid >> 5] = sum; s_red[(tid >> 5) + 8] = sq; }
    __syncthreads();
    if (tid == 0) {
        float S = 0.f, Q = 0.f;
        #pragma unroll
        for (int i = 0; i < 8; i++) { S += s_red[i]; Q += s_red[i + 8]; }
        float mu  = S * (1.f / Mc);
        float var = Q * (1.f / Mc) - mu * mu;
        s_red[16] = mu;
        s_red[17] = rsqrtf(var + 1e-5f);
    }
    // stage Wq (padded pitch 65 -> conflict-free column reads)
    for (int i = tid; i < Ec * Kc; i += 256)
        s_wq[(i >> 6) * 65 + (i & 63)] = Wq[i];
    __syncthreads();

    const float mu = s_red[16], rstd = s_red[17];
    for (int i = tid; i < Mc; i += 256)
        s_y[i] = (s_y[i] - mu) * rstd * gamma[i] + beta[i];
    __syncthreads();

    // GEMM: each thread owns e = (tid&63) + 64j (j<4), n rows (tid>>6)*16 .. +15
    const int e_base = tid & 63;
    const int ty = tid >> 6;
    for (int c = 0; c < 16; c += 2) {
        const int n0 = ty * 16 + c;
        float acc[2][4] = {};
        const float* y0 = s_y + n0 * 64;
        #pragma unroll 8
        for (int k = 0; k < 64; k++) {
            float a0 = y0[k];
            float a1 = y0[64 + k];
            #pragma unroll
            for (int j = 0; j < 4; j++) {
                float wv = s_wq[(e_base + 64 * j) * 65 + k];
                acc[0][j] += a0 * wv;
                acc[1][j] += a1 * wv;
            }
        }
        #pragma unroll
        for (int i = 0; i < 2; i++)
            #pragma unroll
            for (int j = 0; j < 4; j++) {
                int e = e_base + 64 * j;
                int h = e >> 5, d = e & 31;
                g_q[(((size_t)(b * Hc + h) * Nc) + (n0 + i)) * DKc + d] = acc[i][j];
            }
    }
}

// ---------------------------------------------------------------------------
// Kernel 2: per-(b,h): gather kf, key GEMM, conv-V, scores, softmax(+attn out),
//           out = attn @ v -> g_o
// grid = (H, B), block = 256
// ---------------------------------------------------------------------------
static constexpr int SMEM2 =
    (64 * 67 + 64 * 65 + 32 * 65 + 64 * 33 + 64 * 65 + 2048 + 16) * 4;

__global__ __launch_bounds__(256) void head_kernel(
    const float* __restrict__ feat, const int* __restrict__ sidx,
    const float* __restrict__ Wk, const float* __restrict__ Wv1,
    const float* __restrict__ Wv2, float* __restrict__ attn_out)
{
    extern __shared__ float sm[];
    float* s_kf  = sm;                   // 64 x 67 (cols 64,65 zeroed for conv tail)
    float* s_v   = s_kf  + 64 * 67;      // 64 x 65
    float* s_key = s_v   + 64 * 65;      // 32 x 65   key[d][n]
    float* s_q   = s_key + 32 * 65;      // 64 x 33   q scaled by 1/64
    float* s_S   = s_q   + 64 * 33;      // 64 x 65
    float* s_wk  = s_S   + 64 * 65;      // 32 x 64
    float* s_wv1 = s_wk  + 2048;         // 12
    float* s_wv2 = s_wv1 + 12;           // 4

    const int h = blockIdx.x, b = blockIdx.y, tid = threadIdx.x;
    const float* xrow = feat + (size_t)b * Mc;
    const int*   idx  = sidx + (size_t)h * Mc;

    for (int i = tid; i < 2048; i += 256) s_wk[i] = Wk[h * 2048 + i];
    if (tid < 12) s_wv1[tid] = Wv1[h * 12 + tid];
    if (tid < 4)  s_wv2[tid] = Wv2[h * 4 + tid];

    // gather (features row is L2-resident) + zero conv pad
    for (int i = tid; i < 4096; i += 256) {
        int n = i >> 6, k = i & 63;
        s_kf[n * 67 + k] = xrow[idx[i]];
    }
    if (tid < 128) s_kf[(tid >> 1) * 67 + 64 + (tid & 1)] = 0.f;

    // q, pre-scaled by softmax 1/sqrt(M) = 1/64
    const float* qg = g_q + ((size_t)(b * Hc + h) * Nc) * DKc;
    for (int i = tid; i < 2048; i += 256) {
        int n = i >> 5, d = i & 31;
        s_q[n * 33 + d] = qg[i] * 0.015625f;
    }
    __syncthreads();

    // key[d][n] = sum_k kf[n][k] * Wk[d][k]   (2d x 4n per thread)
    {
        const int n0 = (tid & 15) * 4, d0 = (tid >> 4) * 2;
        float acc[2][4] = {};
        #pragma unroll 8
        for (int k = 0; k < 64; k++) {
            float w0 = s_wk[d0 * 64 + k], w1 = s_wk[(d0 + 1) * 64 + k];
            #pragma unroll
            for (int i = 0; i < 4; i++) {
                float xv = s_kf[(n0 + i) * 67 + k];
                acc[0][i] += w0 * xv;
                acc[1][i] += w1 * xv;
            }
        }
        #pragma unroll
        for (int j = 0; j < 2; j++)
            #pragma unroll
            for (int i = 0; i < 4; i++)
                s_key[(d0 + j) * 65 + n0 + i] = acc[j][i];
    }

    // v[n][p] = kf[n][p] + sum_d relu(sum_t kf[n][p+t]*Wv1[d][t]) * Wv2[d]
    {
        const int n = tid >> 2, p0 = (tid & 3) * 16;
        const float* kr = s_kf + n * 67;
        float* vr = s_v + n * 65;
        for (int p = p0; p < p0 + 16; p++) {
            float x0 = kr[p], x1 = kr[p + 1], x2 = kr[p + 2];
            float acc = x0;
            #pragma unroll
            for (int d = 0; d < 4; d++) {
                float t = x0 * s_wv1[d * 3] + x1 * s_wv1[d * 3 + 1] + x2 * s_wv1[d * 3 + 2];
                acc += fmaxf(t, 0.f) * s_wv2[d];
            }
            vr[p] = acc;
        }
    }
    __syncthreads();

    // scores S[q][n] = sum_d qs[q][d] * key[d][n]  (4x4 tiles)
    const int q0 = (tid >> 4) * 4, n0 = (tid & 15) * 4;
    {
        float acc[4][4] = {};
        #pragma unroll 4
        for (int d = 0; d < 32; d++) {
            float a[4], bb[4];
            #pragma unroll
            for (int i = 0; i < 4; i++) a[i] = s_q[(q0 + i) * 33 + d];
            #pragma unroll
            for (int j = 0; j < 4; j++) bb[j] = s_key[d * 65 + n0 + j];
            #pragma unroll
            for (int i = 0; i < 4; i++)
                #pragma unroll
                for (int j = 0; j < 4; j++) acc[i][j] += a[i] * bb[j];
        }
        #pragma unroll
        for (int i = 0; i < 4; i++)
            #pragma unroll
            for (int j = 0; j < 4; j++)
                s_S[(q0 + i) * 65 + n0 + j] = acc[i][j];
    }
    __syncthreads();

    // softmax per row (4 lanes per row), write attn to global too
    {
        const int r = tid >> 2, s = tid & 3;
        float* row = s_S + r * 65 + s * 16;
        float mx = -1e30f;
        #pragma unroll
        for (int i = 0; i < 16; i++) mx = fmaxf(mx, row[i]);
        mx = fmaxf(mx, __shfl_xor_sync(~0u, mx, 1));
        mx = fmaxf(mx, __shfl_xor_sync(~0u, mx, 2));
        float ev[16]; float ssum = 0.f;
        #pragma unroll
        for (int i = 0; i < 16; i++) { ev[i] = __expf(row[i] - mx); ssum += ev[i]; }
        ssum += __shfl_xor_sync(~0u, ssum, 1);
        ssum += __shfl_xor_sync(~0u, ssum, 2);
        const float inv = 1.f / ssum;
        float* gattn = attn_out + (((size_t)(b * Hc + h) * Nc + r) * Nc) + s * 16;
        #pragma unroll
        for (int i = 0; i < 16; i++) {
            float p = ev[i] * inv;
            row[i] = p;
            gattn[i] = p;
        }
    }
    __syncthreads();

    // out[q][p] = sum_n S[q][n] * v[n][p] -> g_o[b][q][h*64+p]
    {
        float acc[4][4] = {};
        #pragma unroll 4
        for (int n = 0; n < 64; n++) {
            float a[4], bb[4];
            #pragma unroll
            for (int i = 0; i < 4; i++) a[i] = s_S[(q0 + i) * 65 + n];
            #pragma unroll
            for (int j = 0; j < 4; j++) bb[j] = s_v[n * 65 + n0 + j];
            #pragma unroll
            for (int i = 0; i < 4; i++)
                #pragma unroll
                for (int j = 0; j < 4; j++) acc[i][j] += a[i] * bb[j];
        }
        #pragma unroll
        for (int i = 0; i < 4; i++) {
            float* dst = g_o + ((size_t)(b * Nc + q0 + i) * Fc) + h * Kc + n0;
            #pragma unroll
            for (int j = 0; j < 4; j++) dst[j] = acc[i][j];
        }
    }
}

// ---------------------------------------------------------------------------
// Kernel 3: per-batch FC: out[b,n,o] = sum_f g_o[b,n,f] * Wfc[o,f]
// grid = B, block = 256. smem: O[64][513] + W chunk [64][129]
// ---------------------------------------------------------------------------
static constexpr int SMEM3 = (64 * 513 + 64 * 129) * 4;

__global__ __launch_bounds__(256) void fc_kernel(
    const float* __restrict__ Wfc, float* __restrict__ out)
{
    extern __shared__ float sm[];
    float* s_O = sm;               // 64 x 513
    float* s_W = sm + 64 * 513;    // 64 x 129

    const int b = blockIdx.x, tid = threadIdx.x;
    const float* O = g_o + (size_t)b * Nc * Fc;

    for (int i = tid; i < Nc * Fc; i += 256)
        s_O[(i >> 9) * 513 + (i & 511)] = O[i];

    const int o0 = tid & 15;          // o = o0 + 16j
    const int n0 = (tid >> 4) * 4;    // 4 rows
    float acc[4][4] = {};

    for (int fc = 0; fc < 4; fc++) {
        __syncthreads();
        for (int i = tid; i < 64 * 128; i += 256) {
            int o = i >> 7, f = i & 127;
            s_W[o * 129 + f] = Wfc[o * 512 + fc * 128 + f];
        }
        __syncthreads();
        #pragma unroll 4
        for (int f = 0; f < 128; f++) {
            float a[4], w[4];
            #pragma unroll
            for (int i = 0; i < 4; i++) a[i] = s_O[(n0 + i) * 513 + fc * 128 + f];
            #pragma unroll
            for (int j = 0; j < 4; j++) w[j] = s_W[(o0 + 16 * j) * 129 + f];
            #pragma unroll
            for (int i = 0; i < 4; i++)
                #pragma unroll
                for (int j = 0; j < 4; j++) acc[i][j] += a[i] * w[j];
        }
    }
    #pragma unroll
    for (int i = 0; i < 4; i++)
        #pragma unroll
        for (int j = 0; j < 4; j++)
            out[(size_t)b * 4096 + (n0 + i) * 64 + o0 + 16 * j] = acc[i][j];
}

// ---------------------------------------------------------------------------
extern "C" void kernel_launch(void* const* d_in, const int* in_sizes, int n_in,
                              void* d_out, int out_size) {
    const float* feat  = (const float*)d_in[0];
    const int*   sidx  = (const int*)  d_in[1];
    const float* gamma = (const float*)d_in[2];
    const float* beta  = (const float*)d_in[3];
    const float* Wq    = (const float*)d_in[4];
    const float* Wk    = (const float*)d_in[5];
    const float* Wv1   = (const float*)d_in[6];
    const float* Wv2   = (const float*)d_in[7];
    const float* Wfc   = (const float*)d_in[8];

    float* out  = (float*)d_out;
    float* attn = out + (size_t)Bc * Nc * DOUTc;   // out (512*4096), then attn (4096*64*64)

    cudaFuncSetAttribute(ln_q_kernel, cudaFuncAttributeMaxDynamicSharedMemorySize, SMEM1);
    cudaFuncSetAttribute(head_kernel, cudaFuncAttributeMaxDynamicSharedMemorySize, SMEM2);
    cudaFuncSetAttribute(fc_kernel,   cudaFuncAttributeMaxDynamicSharedMemorySize, SMEM3);

    ln_q_kernel<<<Bc, 256, SMEM1>>>(feat, gamma, beta, Wq);
    head_kernel<<<dim3(Hc, Bc), 256, SMEM2>>>(feat, sidx, Wk, Wv1, Wv2, attn);
    fc_kernel<<<Bc, 256, SMEM3>>>(Wfc, out);
}

// round 2
// speedup vs baseline: 1.5785x; 1.5785x over previous
#include <cuda_runtime.h>
#include <math.h>

#define Bc 512
#define Mc 4096
#define Nc 64
#define Kc 64
#define Hc 8
#define DKc 32

// Scratch (device globals, allocation-free rule)
__device__ float g_q[(size_t)Bc * Hc * Nc * DKc];   // 32 MB, (b,h,n,d), pre-scaled 1/64
__device__ float g_o[(size_t)Bc * Nc * 512];        // 64 MB, (b,n, h*64+p)
__device__ float g_wqT[64 * 256];                   // Wq transposed: [k][e]
__device__ float g_wfcT[512 * 64];                  // Wfc transposed: [f][o]

// ---------------------------------------------------------------------------
// Kernel 0: transpose weights (one-time per launch, ~48K elements)
// ---------------------------------------------------------------------------
__global__ void transpose_w(const float* __restrict__ Wq,
                            const float* __restrict__ Wfc)
{
    int i = blockIdx.x * 256 + threadIdx.x;
    if (blockIdx.y == 0) {
        if (i < 256 * 64) { int e = i >> 6, k = i & 63; g_wqT[k * 256 + e] = Wq[i]; }
    } else {
        if (i < 64 * 512) { int o = i >> 9, f = i & 511; g_wfcT[f * 64 + o] = Wfc[i]; }
    }
}

// ---------------------------------------------------------------------------
// Kernel 1: per-batch LayerNorm + Q projection (pre-scaled by 1/sqrt(M)=1/64)
// grid = B, block = 256. smem: y[4096] + wT chunk [64k][64e] = 32 KB
// ---------------------------------------------------------------------------
static constexpr int SMEM1 = (4096 + 64 * 64) * 4;

__global__ __launch_bounds__(256) void ln_q_kernel(
    const float* __restrict__ feat, const float* __restrict__ gamma,
    const float* __restrict__ beta)
{
    extern __shared__ float sm[];
    float* s_y = sm;          // 4096
    float* s_w = sm + 4096;   // 64 x 64, [k][e_local]
    __shared__ float s_red[18];

    const int b = blockIdx.x, tid = threadIdx.x;
    const float* x = feat + (size_t)b * Mc;

    float sum = 0.f, sq = 0.f;
    for (int i = tid; i < Mc; i += 256) {
        float v = x[i];
        s_y[i] = v; sum += v; sq += v * v;
    }
    #pragma unroll
    for (int o = 16; o; o >>= 1) {
        sum += __shfl_xor_sync(~0u, sum, o);
        sq  += __shfl_xor_sync(~0u, sq,  o);
    }
    if ((tid & 31) == 0) { s_red[tid >> 5] = sum; s_red[(tid >> 5) + 8] = sq; }
    __syncthreads();
    if (tid == 0) {
        float S = 0.f, Q = 0.f;
        #pragma unroll
        for (int i = 0; i < 8; i++) { S += s_red[i]; Q += s_red[i + 8]; }
        float mu  = S * (1.f / Mc);
        float var = Q * (1.f / Mc) - mu * mu;
        s_red[16] = mu;
        s_red[17] = rsqrtf(var + 1e-5f);
    }
    __syncthreads();
    const float mu = s_red[16], rstd = s_red[17];
    for (int i = tid; i < Mc; i += 256)
        s_y[i] = (s_y[i] - mu) * rstd * gamma[i] + beta[i];

    const int e0 = (tid & 15) * 4;       // e within chunk (contiguous b-loads)
    const int n0 = (tid >> 4) * 4;       // broadcast a-loads
    for (int chunk = 0; chunk < 4; chunk++) {
        __syncthreads();
        // stage wT chunk: s_w[k][e] = g_wqT[k][chunk*64 + e]
        for (int i = tid; i < 4096; i += 256)
            s_w[i] = g_wqT[(i >> 6) * 256 + chunk * 64 + (i & 63)];
        __syncthreads();

        float acc[4][4] = {};
        #pragma unroll
        for (int k4 = 0; k4 < 16; k4++) {
            float4 a[4], bv[4];
            #pragma unroll
            for (int i = 0; i < 4; i++)
                a[i] = *(const float4*)&s_y[(n0 + i) * 64 + k4 * 4];
            #pragma unroll
            for (int kk = 0; kk < 4; kk++)
                bv[kk] = *(const float4*)&s_w[(k4 * 4 + kk) * 64 + e0];
            #pragma unroll
            for (int i = 0; i < 4; i++) {
                acc[i][0] += a[i].x * bv[0].x + a[i].y * bv[1].x + a[i].z * bv[2].x + a[i].w * bv[3].x;
                acc[i][1] += a[i].x * bv[0].y + a[i].y * bv[1].y + a[i].z * bv[2].y + a[i].w * bv[3].y;
                acc[i][2] += a[i].x * bv[0].z + a[i].y * bv[1].z + a[i].z * bv[2].z + a[i].w * bv[3].z;
                acc[i][3] += a[i].x * bv[0].w + a[i].y * bv[1].w + a[i].z * bv[2].w + a[i].w * bv[3].w;
            }
        }
        const int eg = chunk * 64 + e0;
        const int h = eg >> 5, d = eg & 31;
        #pragma unroll
        for (int i = 0; i < 4; i++) {
            float4 st = make_float4(acc[i][0] * 0.015625f, acc[i][1] * 0.015625f,
                                    acc[i][2] * 0.015625f, acc[i][3] * 0.015625f);
            *(float4*)&g_q[(((size_t)(b * Hc + h) * Nc) + n0 + i) * DKc + d] = st;
        }
    }
}

// ---------------------------------------------------------------------------
// Kernel 2: per-(b,h) head. smem 51.3 KB -> 4 CTA/SM.
// regions: kf(64x68)/S(64x64 overlay) | v(64x68) | key(32x64) | wk(32x64)->q(64x32) | wv(16)
// ---------------------------------------------------------------------------
static constexpr int SMEM2 = (64 * 68 + 64 * 68 + 32 * 64 + 2048 + 16) * 4;

__global__ __launch_bounds__(256) void head_kernel(
    const float* __restrict__ feat, const int* __restrict__ sidx,
    const float* __restrict__ Wk, const float* __restrict__ Wv1,
    const float* __restrict__ Wv2, float* __restrict__ attn_out)
{
    extern __shared__ float sm[];
    float* s_kf  = sm;                 // 64 x 68 (cols 64,65 zero for conv); later S (64 x 64)
    float* s_S   = sm;
    float* s_v   = sm + 64 * 68;       // 64 x 68
    float* s_key = s_v + 64 * 68;      // 32 x 64  key[d][n]
    float* s_wk  = s_key + 32 * 64;    // 32 x 64 -> later q[64][32]
    float* s_q   = s_wk;
    float* s_wv1 = s_wk + 2048;        // 12
    float* s_wv2 = s_wv1 + 12;         // 4

    const int h = blockIdx.x, b = blockIdx.y, tid = threadIdx.x;
    const float* xrow = feat + (size_t)b * Mc;
    const int*   idx  = sidx + (size_t)h * Mc;

    // -------- phase 1: stage kf (gathered), wk, wv --------
    for (int i = tid; i < 2048; i += 256) s_wk[i] = Wk[h * 2048 + i];
    if (tid < 12) s_wv1[tid] = Wv1[h * 12 + tid];
    if (tid >= 32 && tid < 36) s_wv2[tid - 32] = Wv2[h * 4 + tid - 32];
    for (int i = tid; i < 4096; i += 256)
        s_kf[(i >> 6) * 68 + (i & 63)] = xrow[idx[i]];
    if (tid < 128) s_kf[(tid >> 1) * 68 + 64 + (tid & 1)] = 0.f;
    __syncthreads();

    // -------- phase 2a: key[d][n] = sum_k kf[n][k] * wk[d][k] --------
    {
        const int nx = tid & 15;           // n in {nx, nx+16, nx+32, nx+48}
        const int d0 = (tid >> 4) * 2;     // 2 d rows (broadcast)
        float acc[2][4] = {};
        #pragma unroll
        for (int k4 = 0; k4 < 16; k4++) {
            float4 a[4], w[2];
            #pragma unroll
            for (int s = 0; s < 4; s++)
                a[s] = *(const float4*)&s_kf[(nx + 16 * s) * 68 + k4 * 4];
            #pragma unroll
            for (int t = 0; t < 2; t++)
                w[t] = *(const float4*)&s_wk[(d0 + t) * 64 + k4 * 4];
            #pragma unroll
            for (int t = 0; t < 2; t++)
                #pragma unroll
                for (int s = 0; s < 4; s++)
                    acc[t][s] += a[s].x * w[t].x + a[s].y * w[t].y +
                                 a[s].z * w[t].z + a[s].w * w[t].w;
        }
        #pragma unroll
        for (int t = 0; t < 2; t++)
            #pragma unroll
            for (int s = 0; s < 4; s++)
                s_key[(d0 + t) * 64 + nx + 16 * s] = acc[t][s];
    }

    // -------- phase 2b: v[n][p] = kf[n][p] + sum_d relu(conv3(kf)) * wv2 --------
    {
        const int n = tid >> 2, p0 = (tid & 3) * 16;
        const float* kr = s_kf + n * 68;
        float* vr = s_v + n * 68;
        float w0[4], w1[4], w2[4], w3[4];
        #pragma unroll
        for (int d = 0; d < 4; d++) {
            w0[d] = s_wv1[d * 3]; w1[d] = s_wv1[d * 3 + 1];
            w2[d] = s_wv1[d * 3 + 2]; w3[d] = s_wv2[d];
        }
        #pragma unroll
        for (int p = p0; p < p0 + 16; p++) {
            float x0 = kr[p], x1 = kr[p + 1], x2 = kr[p + 2];
            float acc = x0;
            #pragma unroll
            for (int d = 0; d < 4; d++)
                acc += fmaxf(x0 * w0[d] + x1 * w1[d] + x2 * w2[d], 0.f) * w3[d];
            vr[p] = acc;
        }
    }
    __syncthreads();

    // -------- phase 3: load q (overlays wk), pre-scaled in ln_q --------
    {
        const float* qg = g_q + ((size_t)(b * Hc + h) * Nc) * DKc;
        for (int i = tid; i < 2048; i += 256) s_q[i] = qg[i];
    }
    __syncthreads();

    const int q0 = (tid >> 4) * 4;   // broadcast side
    const int n0 = (tid & 15) * 4;   // contiguous side

    // -------- phase 4: S[q][n] = sum_d q[q][d] * key[d][n] --------
    {
        float acc[4][4] = {};
        #pragma unroll
        for (int d4 = 0; d4 < 8; d4++) {
            float4 a[4], bv[4];
            #pragma unroll
            for (int i = 0; i < 4; i++)
                a[i] = *(const float4*)&s_q[(q0 + i) * 32 + d4 * 4];
            #pragma unroll
            for (int kk = 0; kk < 4; kk++)
                bv[kk] = *(const float4*)&s_key[(d4 * 4 + kk) * 64 + n0];
            #pragma unroll
            for (int i = 0; i < 4; i++) {
                acc[i][0] += a[i].x * bv[0].x + a[i].y * bv[1].x + a[i].z * bv[2].x + a[i].w * bv[3].x;
                acc[i][1] += a[i].x * bv[0].y + a[i].y * bv[1].y + a[i].z * bv[2].y + a[i].w * bv[3].y;
                acc[i][2] += a[i].x * bv[0].z + a[i].y * bv[1].z + a[i].z * bv[2].z + a[i].w * bv[3].z;
                acc[i][3] += a[i].x * bv[0].w + a[i].y * bv[1].w + a[i].z * bv[2].w + a[i].w * bv[3].w;
            }
        }
        __syncthreads();   // kf fully consumed before S overlays it
        #pragma unroll
        for (int i = 0; i < 4; i++)
            *(float4*)&s_S[(q0 + i) * 64 + n0] =
                make_float4(acc[i][0], acc[i][1], acc[i][2], acc[i][3]);
    }
    __syncthreads();

    // -------- phase 5: softmax rows of S, also write attn to global --------
    {
        const int r = tid >> 2, s3 = tid & 3;
        float* row = s_S + r * 64 + s3 * 16;
        float4 v0 = *(float4*)&row[0], v1 = *(float4*)&row[4];
        float4 v2 = *(float4*)&row[8], v3 = *(float4*)&row[12];
        float mx = fmaxf(fmaxf(fmaxf(v0.x, v0.y), fmaxf(v0.z, v0.w)),
                         fmaxf(fmaxf(v1.x, v1.y), fmaxf(v1.z, v1.w)));
        mx = fmaxf(mx, fmaxf(fmaxf(fmaxf(v2.x, v2.y), fmaxf(v2.z, v2.w)),
                             fmaxf(fmaxf(v3.x, v3.y), fmaxf(v3.z, v3.w))));
        mx = fmaxf(mx, __shfl_xor_sync(~0u, mx, 1));
        mx = fmaxf(mx, __shfl_xor_sync(~0u, mx, 2));
        float e[16];
        e[0]=__expf(v0.x-mx); e[1]=__expf(v0.y-mx); e[2]=__expf(v0.z-mx); e[3]=__expf(v0.w-mx);
        e[4]=__expf(v1.x-mx); e[5]=__expf(v1.y-mx); e[6]=__expf(v1.z-mx); e[7]=__expf(v1.w-mx);
        e[8]=__expf(v2.x-mx); e[9]=__expf(v2.y-mx); e[10]=__expf(v2.z-mx); e[11]=__expf(v2.w-mx);
        e[12]=__expf(v3.x-mx); e[13]=__expf(v3.y-mx); e[14]=__expf(v3.z-mx); e[15]=__expf(v3.w-mx);
        float ssum = 0.f;
        #pragma unroll
        for (int i = 0; i < 16; i++) ssum += e[i];
        ssum += __shfl_xor_sync(~0u, ssum, 1);
        ssum += __shfl_xor_sync(~0u, ssum, 2);
        const float inv = 1.f / ssum;
        float* gattn = attn_out + (((size_t)(b * Hc + h) * Nc + r) * Nc) + s3 * 16;
        #pragma unroll
        for (int u = 0; u < 4; u++) {
            float4 p = make_float4(e[4*u] * inv, e[4*u+1] * inv, e[4*u+2] * inv, e[4*u+3] * inv);
            *(float4*)&row[4 * u] = p;
            *(float4*)&gattn[4 * u] = p;
        }
    }
    __syncthreads();

    // -------- phase 6: out[q][p] = sum_n S[q][n] * v[n][p] --------
    {
        float acc[4][4] = {};
        #pragma unroll
        for (int n4 = 0; n4 < 16; n4++) {
            float4 a[4], bv[4];
            #pragma unroll
            for (int i = 0; i < 4; i++)
                a[i] = *(const float4*)&s_S[(q0 + i) * 64 + n4 * 4];
            #pragma unroll
            for (int kk = 0; kk < 4; kk++)
                bv[kk] = *(const float4*)&s_v[(n4 * 4 + kk) * 68 + n0];
            #pragma unroll
            for (int i = 0; i < 4; i++) {
                acc[i][0] += a[i].x * bv[0].x + a[i].y * bv[1].x + a[i].z * bv[2].x + a[i].w * bv[3].x;
                acc[i][1] += a[i].x * bv[0].y + a[i].y * bv[1].y + a[i].z * bv[2].y + a[i].w * bv[3].y;
                acc[i][2] += a[i].x * bv[0].z + a[i].y * bv[1].z + a[i].z * bv[2].z + a[i].w * bv[3].z;
                acc[i][3] += a[i].x * bv[0].w + a[i].y * bv[1].w + a[i].z * bv[2].w + a[i].w * bv[3].w;
            }
        }
        #pragma unroll
        for (int i = 0; i < 4; i++)
            *(float4*)&g_o[((size_t)(b * Nc + q0 + i) * 512) + h * 64 + n0] =
                make_float4(acc[i][0], acc[i][1], acc[i][2], acc[i][3]);
    }
}

// ---------------------------------------------------------------------------
// Kernel 3: FC GEMM out[b,n,o] = sum_f g_o[b,n,f] * WfcT[f,o]
// grid = B, block = 256. smem: A 64x68 + W 64x64 = 33.8 KB
// ---------------------------------------------------------------------------
static constexpr int SMEM3 = (64 * 68 + 64 * 64) * 4;

__global__ __launch_bounds__(256) void fc_kernel(float* __restrict__ out)
{
    extern __shared__ float sm[];
    float* s_A = sm;              // 64 x 68
    float* s_W = sm + 64 * 68;    // 64 x 64, [f_local][o]

    const int b = blockIdx.x, tid = threadIdx.x;
    const float* O = g_o + (size_t)b * Nc * 512;

    const int m0 = (tid >> 4) * 4;    // n rows (broadcast)
    const int o0 = (tid & 15) * 4;    // o cols (contiguous)
    float acc[4][4] = {};

    for (int kc = 0; kc < 8; kc++) {
        __syncthreads();
        for (int i = tid; i < 4096; i += 256) {
            int n = i >> 6, k = i & 63;
            s_A[n * 68 + k] = O[n * 512 + kc * 64 + k];
        }
        for (int i = tid; i < 4096; i += 256)
            s_W[i] = g_wfcT[(kc * 64 + (i >> 6)) * 64 + (i & 63)];
        __syncthreads();
        #pragma unroll
        for (int k4 = 0; k4 < 16; k4++) {
            float4 a[4], bv[4];
            #pragma unroll
            for (int i = 0; i < 4; i++)
                a[i] = *(const float4*)&s_A[(m0 + i) * 68 + k4 * 4];
            #pragma unroll
            for (int kk = 0; kk < 4; kk++)
                bv[kk] = *(const float4*)&s_W[(k4 * 4 + kk) * 64 + o0];
            #pragma unroll
            for (int i = 0; i < 4; i++) {
                acc[i][0] += a[i].x * bv[0].x + a[i].y * bv[1].x + a[i].z * bv[2].x + a[i].w * bv[3].x;
                acc[i][1] += a[i].x * bv[0].y + a[i].y * bv[1].y + a[i].z * bv[2].y + a[i].w * bv[3].y;
                acc[i][2] += a[i].x * bv[0].z + a[i].y * bv[1].z + a[i].z * bv[2].z + a[i].w * bv[3].z;
                acc[i][3] += a[i].x * bv[0].w + a[i].y * bv[1].w + a[i].z * bv[2].w + a[i].w * bv[3].w;
            }
        }
    }
    #pragma unroll
    for (int i = 0; i < 4; i++)
        *(float4*)&out[(size_t)b * 4096 + (m0 + i) * 64 + o0] =
            make_float4(acc[i][0], acc[i][1], acc[i][2], acc[i][3]);
}

// ---------------------------------------------------------------------------
extern "C" void kernel_launch(void* const* d_in, const int* in_sizes, int n_in,
                              void* d_out, int out_size) {
    const float* feat  = (const float*)d_in[0];
    const int*   sidx  = (const int*)  d_in[1];
    const float* gamma = (const float*)d_in[2];
    const float* beta  = (const float*)d_in[3];
    const float* Wq    = (const float*)d_in[4];
    const float* Wk    = (const float*)d_in[5];
    const float* Wv1   = (const float*)d_in[6];
    const float* Wv2   = (const float*)d_in[7];
    const float* Wfc   = (const float*)d_in[8];

    float* out  = (float*)d_out;
    float* attn = out + (size_t)Bc * Nc * 64;   // out (512*4096) then attn (4096*64*64)

    cudaFuncSetAttribute(ln_q_kernel, cudaFuncAttributeMaxDynamicSharedMemorySize, SMEM1);
    cudaFuncSetAttribute(head_kernel, cudaFuncAttributeMaxDynamicSharedMemorySize, SMEM2);
    cudaFuncSetAttribute(fc_kernel,   cudaFuncAttributeMaxDynamicSharedMemorySize, SMEM3);

    transpose_w<<<dim3(128, 2), 256>>>(Wq, Wfc);
    ln_q_kernel<<<Bc, 256, SMEM1>>>(feat, gamma, beta);
    head_kernel<<<dim3(Hc, Bc), 256, SMEM2>>>(feat, sidx, Wk, Wv1, Wv2, attn);
    fc_kernel<<<Bc, 256, SMEM3>>>(out);
}

// round 4
// speedup vs baseline: 1.7716x; 1.1223x over previous
#include <cuda_runtime.h>
#include <math.h>
#include <stdint.h>

#define Bc 512
#define Mc 4096
#define Nc 64
#define Hc 8

// Scratch (device globals, allocation-free rule)
__device__ float g_q[(size_t)Bc * Hc * Nc * 32];    // 32 MB, (b,h,n,d), pre-scaled 1/64
__device__ float g_o[(size_t)Bc * Nc * 512];        // 64 MB, (b,n, h*64+p)

__device__ __forceinline__ float tf32r(float x) {
    float r; asm("cvt.rna.tf32.f32 %0, %1;" : "=f"(r) : "f"(x)); return r;
}
__device__ __forceinline__ void mma16n8k8(float* c, const uint32_t* a, const uint32_t* b) {
    asm volatile(
        "mma.sync.aligned.m16n8k8.row.col.f32.tf32.tf32.f32 "
        "{%0,%1,%2,%3}, {%4,%5,%6,%7}, {%8,%9}, {%0,%1,%2,%3};"
        : "+f"(c[0]), "+f"(c[1]), "+f"(c[2]), "+f"(c[3])
        : "r"(a[0]), "r"(a[1]), "r"(a[2]), "r"(a[3]), "r"(b[0]), "r"(b[1]));
}

// ---------------------------------------------------------------------------
// Kernel 1: per-batch LayerNorm + Q projection via mma.sync tf32.
// grid = B, block = 256 (8 warps).
// q[n][e] = sum_k y[n][k] * Wq[e][k]; M=64, N=256 (2 chunks of 128), K=64.
// smem: y 64x68 + Wq chunk 128x68 = 52.2 KB
// ---------------------------------------------------------------------------
static constexpr int SMEM1 = (64 * 68 + 128 * 68) * 4 + 64;

__global__ __launch_bounds__(256) void ln_q_mma(
    const float* __restrict__ feat, const float* __restrict__ gamma,
    const float* __restrict__ beta, const float* __restrict__ Wq)
{
    extern __shared__ float sm[];
    float* s_y = sm;                 // [n][k] pitch 68
    float* s_w = sm + 64 * 68;       // [e_loc][k] pitch 68
    float* s_red = sm + 64 * 68 + 128 * 68;  // 18

    const int b = blockIdx.x, tid = threadIdx.x;
    const int wid = tid >> 5, lane = tid & 31;
    const int lr = lane >> 2, lc = lane & 3;
    const float* x = feat + (size_t)b * Mc;

    // ---- load raw x into pitched smem + stats ----
    float sum = 0.f, sq = 0.f;
    for (int i = tid; i < Mc; i += 256) {
        float v = x[i];
        s_y[(i >> 6) * 68 + (i & 63)] = v;
        sum += v; sq += v * v;
    }
    #pragma unroll
    for (int o = 16; o; o >>= 1) {
        sum += __shfl_xor_sync(~0u, sum, o);
        sq  += __shfl_xor_sync(~0u, sq,  o);
    }
    if (lane == 0) { s_red[wid] = sum; s_red[wid + 8] = sq; }
    __syncthreads();
    if (tid == 0) {
        float S = 0.f, Q = 0.f;
        #pragma unroll
        for (int i = 0; i < 8; i++) { S += s_red[i]; Q += s_red[i + 8]; }
        float mu = S * (1.f / Mc);
        s_red[16] = mu;
        s_red[17] = rsqrtf(Q * (1.f / Mc) - mu * mu + 1e-5f);
    }
    __syncthreads();
    const float mu = s_red[16], rstd = s_red[17];
    for (int i = tid; i < Mc; i += 256) {
        float* p = &s_y[(i >> 6) * 68 + (i & 63)];
        *p = tf32r((*p - mu) * rstd * gamma[i] + beta[i]);
    }

    // warp tiling: m0 = (wid&3)*16; e-local range n0 = (wid>>2)*64 (8 n8-tiles)
    const int m0 = (wid & 3) * 16;
    const int n0 = (wid >> 2) * 64;

    for (int chunk = 0; chunk < 2; chunk++) {
        __syncthreads();
        for (int i = tid; i < 128 * 64; i += 256)
            s_w[(i >> 6) * 68 + (i & 63)] = tf32r(Wq[(chunk * 128 + (i >> 6)) * 64 + (i & 63)]);
        __syncthreads();

        float acc[8][4] = {};
        #pragma unroll
        for (int k8 = 0; k8 < 8; k8++) {
            const int k0 = k8 * 8;
            uint32_t a[4];
            a[0] = __float_as_uint(s_y[(m0 + lr)     * 68 + k0 + lc]);
            a[1] = __float_as_uint(s_y[(m0 + lr + 8) * 68 + k0 + lc]);
            a[2] = __float_as_uint(s_y[(m0 + lr)     * 68 + k0 + lc + 4]);
            a[3] = __float_as_uint(s_y[(m0 + lr + 8) * 68 + k0 + lc + 4]);
            #pragma unroll
            for (int t = 0; t < 8; t++) {
                uint32_t bfr[2];
                bfr[0] = __float_as_uint(s_w[(n0 + t * 8 + lr) * 68 + k0 + lc]);
                bfr[1] = __float_as_uint(s_w[(n0 + t * 8 + lr) * 68 + k0 + lc + 4]);
                mma16n8k8(acc[t], a, bfr);
            }
        }
        // store: e = chunk*128 + n0 + t*8 + lc*2 ; rows m0+lr, m0+lr+8
        #pragma unroll
        for (int t = 0; t < 8; t++) {
            const int e = chunk * 128 + n0 + t * 8 + lc * 2;
            const int h = e >> 5, d = e & 31;
            float* base = g_q + ((size_t)(b * Hc + h) * Nc) * 32 + d;
            *(float2*)(base + (m0 + lr) * 32)     = make_float2(acc[t][0] * 0.015625f, acc[t][1] * 0.015625f);
            *(float2*)(base + (m0 + lr + 8) * 32) = make_float2(acc[t][2] * 0.015625f, acc[t][3] * 0.015625f);
        }
    }
}

// ---------------------------------------------------------------------------
// Kernel 3: per-batch FC via mma.sync tf32.
// out[n][o] = sum_f A[n][f] * Wfc[o][f]; M=64, N=64, K=512 (4 chunks of 128).
// grid = B, block = 256. smem: A 64x132 + W 64x132 = 67.6 KB
// ---------------------------------------------------------------------------
static constexpr int SMEM3 = (64 * 132 * 2) * 4;

__global__ __launch_bounds__(256) void fc_mma(
    const float* __restrict__ Wfc, float* __restrict__ out)
{
    extern __shared__ float sm[];
    float* s_A = sm;              // [n][f] pitch 132
    float* s_W = sm + 64 * 132;   // [o][f] pitch 132

    const int b = blockIdx.x, tid = threadIdx.x;
    const int wid = tid >> 5, lane = tid & 31;
    const int lr = lane >> 2, lc = lane & 3;
    const float* A = g_o + (size_t)b * Nc * 512;

    const int m0 = (wid >> 1) * 16;   // 4 m-tiles
    const int n0 = (wid & 1) * 32;    // 4 n8-tiles each

    float acc[4][4] = {};

    for (int kc = 0; kc < 4; kc++) {
        __syncthreads();
        // stage A chunk (vectorized + tf32)
        for (int i = tid; i < 2048; i += 256) {
            const int r = i >> 5, k4 = i & 31;
            float4 v = *(const float4*)(A + r * 512 + kc * 128 + k4 * 4);
            v.x = tf32r(v.x); v.y = tf32r(v.y); v.z = tf32r(v.z); v.w = tf32r(v.w);
            *(float4*)&s_A[r * 132 + k4 * 4] = v;
        }
        for (int i = tid; i < 2048; i += 256) {
            const int r = i >> 5, k4 = i & 31;
            float4 v = *(const float4*)(Wfc + r * 512 + kc * 128 + k4 * 4);
            v.x = tf32r(v.x); v.y = tf32r(v.y); v.z = tf32r(v.z); v.w = tf32r(v.w);
            *(float4*)&s_W[r * 132 + k4 * 4] = v;
        }
        __syncthreads();

        #pragma unroll
        for (int k8 = 0; k8 < 16; k8++) {
            const int k0 = k8 * 8;
            uint32_t a[4];
            a[0] = __float_as_uint(s_A[(m0 + lr)     * 132 + k0 + lc]);
            a[1] = __float_as_uint(s_A[(m0 + lr + 8) * 132 + k0 + lc]);
            a[2] = __float_as_uint(s_A[(m0 + lr)     * 132 + k0 + lc + 4]);
            a[3] = __float_as_uint(s_A[(m0 + lr + 8) * 132 + k0 + lc + 4]);
            #pragma unroll
            for (int t = 0; t < 4; t++) {
                uint32_t bfr[2];
                bfr[0] = __float_as_uint(s_W[(n0 + t * 8 + lr) * 132 + k0 + lc]);
                bfr[1] = __float_as_uint(s_W[(n0 + t * 8 + lr) * 132 + k0 + lc + 4]);
                mma16n8k8(acc[t], a, bfr);
            }
        }
    }
    float* ob = out + (size_t)b * 4096;
    #pragma unroll
    for (int t = 0; t < 4; t++) {
        const int o = n0 + t * 8 + lc * 2;
        *(float2*)(ob + (m0 + lr) * 64 + o)     = make_float2(acc[t][0], acc[t][1]);
        *(float2*)(ob + (m0 + lr + 8) * 64 + o) = make_float2(acc[t][2], acc[t][3]);
    }
}

// ---------------------------------------------------------------------------
// Kernel 2: per-(b,h) head (unchanged — proven). smem 51.3 KB.
// ---------------------------------------------------------------------------
static constexpr int SMEM2 = (64 * 68 + 64 * 68 + 32 * 64 + 2048 + 16) * 4;

__global__ __launch_bounds__(256) void head_kernel(
    const float* __restrict__ feat, const int* __restrict__ sidx,
    const float* __restrict__ Wk, const float* __restrict__ Wv1,
    const float* __restrict__ Wv2, float* __restrict__ attn_out)
{
    extern __shared__ float smf[];
    float* s_kf  = smf;
    float* s_S   = smf;
    float* s_v   = smf + 64 * 68;
    float* s_key = s_v + 64 * 68;
    float* s_wk  = s_key + 32 * 64;
    float* s_q   = s_wk;
    float* s_wv1 = s_wk + 2048;
    float* s_wv2 = s_wv1 + 12;

    const int h = blockIdx.x, b = blockIdx.y, tid = threadIdx.x;
    const float* xrow = feat + (size_t)b * Mc;
    const int*   idx  = sidx + (size_t)h * Mc;

    for (int i = tid; i < 2048; i += 256) s_wk[i] = Wk[h * 2048 + i];
    if (tid < 12) s_wv1[tid] = Wv1[h * 12 + tid];
    if (tid >= 32 && tid < 36) s_wv2[tid - 32] = Wv2[h * 4 + tid - 32];
    for (int i = tid; i < 4096; i += 256)
        s_kf[(i >> 6) * 68 + (i & 63)] = xrow[idx[i]];
    if (tid < 128) s_kf[(tid >> 1) * 68 + 64 + (tid & 1)] = 0.f;
    __syncthreads();

    {
        const int nx = tid & 15, d0 = (tid >> 4) * 2;
        float acc[2][4] = {};
        #pragma unroll
        for (int k4 = 0; k4 < 16; k4++) {
            float4 a[4], w[2];
            #pragma unroll
            for (int s = 0; s < 4; s++)
                a[s] = *(const float4*)&s_kf[(nx + 16 * s) * 68 + k4 * 4];
            #pragma unroll
            for (int t = 0; t < 2; t++)
                w[t] = *(const float4*)&s_wk[(d0 + t) * 64 + k4 * 4];
            #pragma unroll
            for (int t = 0; t < 2; t++)
                #pragma unroll
                for (int s = 0; s < 4; s++)
                    acc[t][s] += a[s].x * w[t].x + a[s].y * w[t].y +
                                 a[s].z * w[t].z + a[s].w * w[t].w;
        }
        #pragma unroll
        for (int t = 0; t < 2; t++)
            #pragma unroll
            for (int s = 0; s < 4; s++)
                s_key[(d0 + t) * 64 + nx + 16 * s] = acc[t][s];
    }
    {
        const int n = tid >> 2, p0 = (tid & 3) * 16;
        const float* kr = s_kf + n * 68;
        float* vr = s_v + n * 68;
        float w0[4], w1[4], w2[4], w3[4];
        #pragma unroll
        for (int d = 0; d < 4; d++) {
            w0[d] = s_wv1[d * 3]; w1[d] = s_wv1[d * 3 + 1];
            w2[d] = s_wv1[d * 3 + 2]; w3[d] = s_wv2[d];
        }
        #pragma unroll
        for (int p = p0; p < p0 + 16; p++) {
            float x0 = kr[p], x1 = kr[p + 1], x2 = kr[p + 2];
            float acc = x0;
            #pragma unroll
            for (int d = 0; d < 4; d++)
                acc += fmaxf(x0 * w0[d] + x1 * w1[d] + x2 * w2[d], 0.f) * w3[d];
            vr[p] = acc;
        }
    }
    __syncthreads();
    {
        const float* qg = g_q + ((size_t)(b * Hc + h) * Nc) * 32;
        for (int i = tid; i < 2048; i += 256) s_q[i] = qg[i];
    }
    __syncthreads();

    const int q0 = (tid >> 4) * 4, n0 = (tid & 15) * 4;
    {
        float acc[4][4] = {};
        #pragma unroll
        for (int d4 = 0; d4 < 8; d4++) {
            float4 a[4], bv[4];
            #pragma unroll
            for (int i = 0; i < 4; i++)
                a[i] = *(const float4*)&s_q[(q0 + i) * 32 + d4 * 4];
            #pragma unroll
            for (int kk = 0; kk < 4; kk++)
                bv[kk] = *(const float4*)&s_key[(d4 * 4 + kk) * 64 + n0];
            #pragma unroll
            for (int i = 0; i < 4; i++) {
                acc[i][0] += a[i].x * bv[0].x + a[i].y * bv[1].x + a[i].z * bv[2].x + a[i].w * bv[3].x;
                acc[i][1] += a[i].x * bv[0].y + a[i].y * bv[1].y + a[i].z * bv[2].y + a[i].w * bv[3].y;
                acc[i][2] += a[i].x * bv[0].z + a[i].y * bv[1].z + a[i].z * bv[2].z + a[i].w * bv[3].z;
                acc[i][3] += a[i].x * bv[0].w + a[i].y * bv[1].w + a[i].z * bv[2].w + a[i].w * bv[3].w;
            }
        }
        __syncthreads();
        #pragma unroll
        for (int i = 0; i < 4; i++)
            *(float4*)&s_S[(q0 + i) * 64 + n0] =
                make_float4(acc[i][0], acc[i][1], acc[i][2], acc[i][3]);
    }
    __syncthreads();
    {
        const int r = tid >> 2, s3 = tid & 3;
        float* row = s_S + r * 64 + s3 * 16;
        float4 v0 = *(float4*)&row[0], v1 = *(float4*)&row[4];
        float4 v2 = *(float4*)&row[8], v3 = *(float4*)&row[12];
        float mx = fmaxf(fmaxf(fmaxf(v0.x, v0.y), fmaxf(v0.z, v0.w)),
                         fmaxf(fmaxf(v1.x, v1.y), fmaxf(v1.z, v1.w)));
        mx = fmaxf(mx, fmaxf(fmaxf(fmaxf(v2.x, v2.y), fmaxf(v2.z, v2.w)),
                             fmaxf(fmaxf(v3.x, v3.y), fmaxf(v3.z, v3.w))));
        mx = fmaxf(mx, __shfl_xor_sync(~0u, mx, 1));
        mx = fmaxf(mx, __shfl_xor_sync(~0u, mx, 2));
        float e[16];
        e[0]=__expf(v0.x-mx); e[1]=__expf(v0.y-mx); e[2]=__expf(v0.z-mx); e[3]=__expf(v0.w-mx);
        e[4]=__expf(v1.x-mx); e[5]=__expf(v1.y-mx); e[6]=__expf(v1.z-mx); e[7]=__expf(v1.w-mx);
        e[8]=__expf(v2.x-mx); e[9]=__expf(v2.y-mx); e[10]=__expf(v2.z-mx); e[11]=__expf(v2.w-mx);
        e[12]=__expf(v3.x-mx); e[13]=__expf(v3.y-mx); e[14]=__expf(v3.z-mx); e[15]=__expf(v3.w-mx);
        float ssum = 0.f;
        #pragma unroll
        for (int i = 0; i < 16; i++) ssum += e[i];
        ssum += __shfl_xor_sync(~0u, ssum, 1);
        ssum += __shfl_xor_sync(~0u, ssum, 2);
        const float inv = 1.f / ssum;
        float* gattn = attn_out + (((size_t)(b * Hc + h) * Nc + r) * Nc) + s3 * 16;
        #pragma unroll
        for (int u = 0; u < 4; u++) {
            float4 p = make_float4(e[4*u]*inv, e[4*u+1]*inv, e[4*u+2]*inv, e[4*u+3]*inv);
            *(float4*)&row[4 * u] = p;
            *(float4*)&gattn[4 * u] = p;
        }
    }
    __syncthreads();
    {
        float acc[4][4] = {};
        #pragma unroll
        for (int n4 = 0; n4 < 16; n4++) {
            float4 a[4], bv[4];
            #pragma unroll
            for (int i = 0; i < 4; i++)
                a[i] = *(const float4*)&s_S[(q0 + i) * 64 + n4 * 4];
            #pragma unroll
            for (int kk = 0; kk < 4; kk++)
                bv[kk] = *(const float4*)&s_v[(n4 * 4 + kk) * 68 + n0];
            #pragma unroll
            for (int i = 0; i < 4; i++) {
                acc[i][0] += a[i].x * bv[0].x + a[i].y * bv[1].x + a[i].z * bv[2].x + a[i].w * bv[3].x;
                acc[i][1] += a[i].x * bv[0].y + a[i].y * bv[1].y + a[i].z * bv[2].y + a[i].w * bv[3].y;
                acc[i][2] += a[i].x * bv[0].z + a[i].y * bv[1].z + a[i].z * bv[2].z + a[i].w * bv[3].z;
                acc[i][3] += a[i].x * bv[0].w + a[i].y * bv[1].w + a[i].z * bv[2].w + a[i].w * bv[3].w;
            }
        }
        #pragma unroll
        for (int i = 0; i < 4; i++)
            *(float4*)&g_o[((size_t)(b * Nc + q0 + i) * 512) + h * 64 + n0] =
                make_float4(acc[i][0], acc[i][1], acc[i][2], acc[i][3]);
    }
}

// ---------------------------------------------------------------------------
extern "C" void kernel_launch(void* const* d_in, const int* in_sizes, int n_in,
                              void* d_out, int out_size) {
    const float* feat  = (const float*)d_in[0];
    const int*   sidx  = (const int*)  d_in[1];
    const float* gamma = (const float*)d_in[2];
    const float* beta  = (const float*)d_in[3];
    const float* Wq    = (const float*)d_in[4];
    const float* Wk    = (const float*)d_in[5];
    const float* Wv1   = (const float*)d_in[6];
    const float* Wv2   = (const float*)d_in[7];
    const float* Wfc   = (const float*)d_in[8];

    float* out  = (float*)d_out;
    float* attn = out + (size_t)Bc * Nc * 64;

    cudaFuncSetAttribute(ln_q_mma,    cudaFuncAttributeMaxDynamicSharedMemorySize, SMEM1);
    cudaFuncSetAttribute(head_kernel, cudaFuncAttributeMaxDynamicSharedMemorySize, SMEM2);
    cudaFuncSetAttribute(fc_mma,      cudaFuncAttributeMaxDynamicSharedMemorySize, SMEM3);

    ln_q_mma<<<Bc, 256, SMEM1>>>(feat, gamma, beta, Wq);
    head_kernel<<<dim3(Hc, Bc), 256, SMEM2>>>(feat, sidx, Wk, Wv1, Wv2, attn);
    fc_mma<<<Bc, 256, SMEM3>>>(Wfc, out);
}

// round 5
// speedup vs baseline: 2.2930x; 1.2943x over previous
#include <cuda_runtime.h>
#include <math.h>
#include <stdint.h>

#define Bc 512
#define Mc 4096
#define Nc 64
#define Hc 8

// Scratch (device globals, allocation-free rule)
__device__ float g_q[(size_t)Bc * Hc * Nc * 32];    // 32 MB, (b,h,n,d), pre-scaled 1/64
__device__ float g_o[(size_t)Bc * Nc * 512];        // 64 MB, (b,n, h*64+p)

__device__ __forceinline__ float tf32r(float x) {
    float r; asm("cvt.rna.tf32.f32 %0, %1;" : "=f"(r) : "f"(x)); return r;
}
__device__ __forceinline__ void mma16n8k8(float* c, const uint32_t* a, const uint32_t* b) {
    asm volatile(
        "mma.sync.aligned.m16n8k8.row.col.f32.tf32.tf32.f32 "
        "{%0,%1,%2,%3}, {%4,%5,%6,%7}, {%8,%9}, {%0,%1,%2,%3};"
        : "+f"(c[0]), "+f"(c[1]), "+f"(c[2]), "+f"(c[3])
        : "r"(a[0]), "r"(a[1]), "r"(a[2]), "r"(a[3]), "r"(b[0]), "r"(b[1]));
}

// ---------------------------------------------------------------------------
// Kernel 1: per-batch LayerNorm + Q projection via mma.sync tf32 (unchanged R4).
// ---------------------------------------------------------------------------
static constexpr int SMEM1 = (64 * 68 + 128 * 68) * 4 + 64;

__global__ __launch_bounds__(256) void ln_q_mma(
    const float* __restrict__ feat, const float* __restrict__ gamma,
    const float* __restrict__ beta, const float* __restrict__ Wq)
{
    extern __shared__ float sm[];
    float* s_y = sm;
    float* s_w = sm + 64 * 68;
    float* s_red = sm + 64 * 68 + 128 * 68;

    const int b = blockIdx.x, tid = threadIdx.x;
    const int wid = tid >> 5, lane = tid & 31;
    const int lr = lane >> 2, lc = lane & 3;
    const float* x = feat + (size_t)b * Mc;

    float sum = 0.f, sq = 0.f;
    for (int i = tid; i < Mc; i += 256) {
        float v = x[i];
        s_y[(i >> 6) * 68 + (i & 63)] = v;
        sum += v; sq += v * v;
    }
    #pragma unroll
    for (int o = 16; o; o >>= 1) {
        sum += __shfl_xor_sync(~0u, sum, o);
        sq  += __shfl_xor_sync(~0u, sq,  o);
    }
    if (lane == 0) { s_red[wid] = sum; s_red[wid + 8] = sq; }
    __syncthreads();
    if (tid == 0) {
        float S = 0.f, Q = 0.f;
        #pragma unroll
        for (int i = 0; i < 8; i++) { S += s_red[i]; Q += s_red[i + 8]; }
        float mu = S * (1.f / Mc);
        s_red[16] = mu;
        s_red[17] = rsqrtf(Q * (1.f / Mc) - mu * mu + 1e-5f);
    }
    __syncthreads();
    const float mu = s_red[16], rstd = s_red[17];
    for (int i = tid; i < Mc; i += 256) {
        float* p = &s_y[(i >> 6) * 68 + (i & 63)];
        *p = tf32r((*p - mu) * rstd * gamma[i] + beta[i]);
    }

    const int m0 = (wid & 3) * 16;
    const int n0 = (wid >> 2) * 64;

    for (int chunk = 0; chunk < 2; chunk++) {
        __syncthreads();
        for (int i = tid; i < 128 * 64; i += 256)
            s_w[(i >> 6) * 68 + (i & 63)] = tf32r(Wq[(chunk * 128 + (i >> 6)) * 64 + (i & 63)]);
        __syncthreads();

        float acc[8][4] = {};
        #pragma unroll
        for (int k8 = 0; k8 < 8; k8++) {
            const int k0 = k8 * 8;
            uint32_t a[4];
            a[0] = __float_as_uint(s_y[(m0 + lr)     * 68 + k0 + lc]);
            a[1] = __float_as_uint(s_y[(m0 + lr + 8) * 68 + k0 + lc]);
            a[2] = __float_as_uint(s_y[(m0 + lr)     * 68 + k0 + lc + 4]);
            a[3] = __float_as_uint(s_y[(m0 + lr + 8) * 68 + k0 + lc + 4]);
            #pragma unroll
            for (int t = 0; t < 8; t++) {
                uint32_t bfr[2];
                bfr[0] = __float_as_uint(s_w[(n0 + t * 8 + lr) * 68 + k0 + lc]);
                bfr[1] = __float_as_uint(s_w[(n0 + t * 8 + lr) * 68 + k0 + lc + 4]);
                mma16n8k8(acc[t], a, bfr);
            }
        }
        #pragma unroll
        for (int t = 0; t < 8; t++) {
            const int e = chunk * 128 + n0 + t * 8 + lc * 2;
            const int h = e >> 5, d = e & 31;
            float* base = g_q + ((size_t)(b * Hc + h) * Nc) * 32 + d;
            *(float2*)(base + (m0 + lr) * 32)     = make_float2(acc[t][0] * 0.015625f, acc[t][1] * 0.015625f);
            *(float2*)(base + (m0 + lr + 8) * 32) = make_float2(acc[t][2] * 0.015625f, acc[t][3] * 0.015625f);
        }
    }
}

// ---------------------------------------------------------------------------
// Kernel 2: per-(b,h) head, GEMMs on mma.sync tf32.
// smem (floats): kf[64][68]@0 (->S overlay) | vT[64][68]@4352 (first feat[4096])
//   | keyT[64][36]@8704 | q[64][36]@11008 | wk[32][68]@13312 | wv@15488. 60.6 KB
// ---------------------------------------------------------------------------
static constexpr int SMEM2 = 15504 * 4;

__global__ __launch_bounds__(256) void head_mma(
    const float* __restrict__ feat, const int* __restrict__ sidx,
    const float* __restrict__ Wk, const float* __restrict__ Wv1,
    const float* __restrict__ Wv2, float* __restrict__ attn_out)
{
    extern __shared__ float sm[];
    float* s_kf   = sm;            // [64][68]
    float* s_S    = sm;            // overlay after kf dead
    float* s_vT   = sm + 4352;     // [p][n] pitch 68
    float* s_feat = sm + 4352;     // 4096, dead after gather
    float* s_keyT = sm + 8704;     // [n][d] pitch 36
    float* s_q    = sm + 11008;    // [q][d] pitch 36
    float* s_wk   = sm + 13312;    // [d][k] pitch 68
    float* s_wv   = sm + 15488;    // wv1[12], wv2[4]

    const int h = blockIdx.x, b = blockIdx.y, tid = threadIdx.x;
    const int wid = tid >> 5, lane = tid & 31;
    const int lr = lane >> 2, lc = lane & 3;
    const int* idx = sidx + (size_t)h * Mc;

    // ---- P0: stage feat (coalesced), wk (tf32), q (tf32), wv ----
    {
        const float4* xr = (const float4*)(feat + (size_t)b * Mc);
        float4* fr = (float4*)s_feat;
        for (int i = tid; i < 1024; i += 256) fr[i] = xr[i];
        for (int i = tid; i < 2048; i += 256)
            s_wk[(i >> 6) * 68 + (i & 63)] = tf32r(Wk[h * 2048 + i]);
        const float* qg = g_q + ((size_t)(b * Hc + h) * Nc) * 32;
        for (int i = tid; i < 2048; i += 256)
            s_q[(i >> 5) * 36 + (i & 31)] = tf32r(qg[i]);
        if (tid < 12) s_wv[tid] = Wv1[h * 12 + tid];
        if (tid >= 32 && tid < 36) s_wv[12 + tid - 32] = Wv2[h * 4 + tid - 32];
    }
    __syncthreads();

    // ---- P1: gather kf from smem feat; zero conv pad ----
    for (int i = tid; i < 4096; i += 256)
        s_kf[(i >> 6) * 68 + (i & 63)] = s_feat[idx[i]];
    if (tid < 128) s_kf[(tid >> 1) * 68 + 64 + (tid & 1)] = 0.f;
    __syncthreads();

    // ---- P2a: key GEMM  keyT[n][d] = sum_k kf[n][k] * wk[d][k] ----
    {
        const int m0 = (wid & 1) * 16;        // d tile
        const int nb = (wid >> 1) * 8;        // ntiles {nb, nb+32}
        float acc[2][4] = {};
        #pragma unroll
        for (int k8 = 0; k8 < 8; k8++) {
            const int k0 = k8 * 8;
            uint32_t a[4];
            a[0] = __float_as_uint(s_wk[(m0 + lr)     * 68 + k0 + lc]);
            a[1] = __float_as_uint(s_wk[(m0 + lr + 8) * 68 + k0 + lc]);
            a[2] = __float_as_uint(s_wk[(m0 + lr)     * 68 + k0 + lc + 4]);
            a[3] = __float_as_uint(s_wk[(m0 + lr + 8) * 68 + k0 + lc + 4]);
            #pragma unroll
            for (int t = 0; t < 2; t++) {
                const int nn = nb + t * 32;
                uint32_t bfr[2];
                bfr[0] = __float_as_uint(tf32r(s_kf[(nn + lr) * 68 + k0 + lc]));
                bfr[1] = __float_as_uint(tf32r(s_kf[(nn + lr) * 68 + k0 + lc + 4]));
                mma16n8k8(acc[t], a, bfr);
            }
        }
        #pragma unroll
        for (int t = 0; t < 2; t++) {
            const int n = nb + t * 32 + lc * 2, d = m0 + lr;
            s_keyT[n * 36 + d]           = tf32r(acc[t][0]);
            s_keyT[(n + 1) * 36 + d]     = tf32r(acc[t][1]);
            s_keyT[n * 36 + d + 8]       = tf32r(acc[t][2]);
            s_keyT[(n + 1) * 36 + d + 8] = tf32r(acc[t][3]);
        }
    }
    // ---- P2b: conv -> vT[p][n] = tf32(kf[n][p] + sum_d relu(conv3)*wv2) ----
    {
        const int n = tid >> 2, p0 = (tid & 3) * 16;
        const float* kr = s_kf + n * 68;
        float w0[4], w1[4], w2[4], w3[4];
        #pragma unroll
        for (int d = 0; d < 4; d++) {
            w0[d] = s_wv[d * 3]; w1[d] = s_wv[d * 3 + 1];
            w2[d] = s_wv[d * 3 + 2]; w3[d] = s_wv[12 + d];
        }
        float x0 = kr[p0], x1 = kr[p0 + 1];
        #pragma unroll
        for (int i = 0; i < 16; i++) {
            float x2 = kr[p0 + i + 2];
            float acc = x0;
            #pragma unroll
            for (int d = 0; d < 4; d++)
                acc += fmaxf(x0 * w0[d] + x1 * w1[d] + x2 * w2[d], 0.f) * w3[d];
            s_vT[(p0 + i) * 68 + n] = tf32r(acc);
            x0 = x1; x1 = x2;
        }
    }
    __syncthreads();

    const int m0 = (wid >> 1) * 16;       // q tile
    const int nb4 = (wid & 1) * 4;        // 4 n-tiles

    // ---- P3: S[q][n] = sum_d q[q][d] * keyT[n][d]  (kf dead -> S overlay) ----
    {
        float acc[4][4] = {};
        #pragma unroll
        for (int k8 = 0; k8 < 4; k8++) {
            const int k0 = k8 * 8;
            uint32_t a[4];
            a[0] = __float_as_uint(s_q[(m0 + lr)     * 36 + k0 + lc]);
            a[1] = __float_as_uint(s_q[(m0 + lr + 8) * 36 + k0 + lc]);
            a[2] = __float_as_uint(s_q[(m0 + lr)     * 36 + k0 + lc + 4]);
            a[3] = __float_as_uint(s_q[(m0 + lr + 8) * 36 + k0 + lc + 4]);
            #pragma unroll
            for (int j = 0; j < 4; j++) {
                const int nn = (nb4 + j) * 8;
                uint32_t bfr[2];
                bfr[0] = __float_as_uint(s_keyT[(nn + lr) * 36 + k0 + lc]);
                bfr[1] = __float_as_uint(s_keyT[(nn + lr) * 36 + k0 + lc + 4]);
                mma16n8k8(acc[j], a, bfr);
            }
        }
        #pragma unroll
        for (int j = 0; j < 4; j++) {
            const int col = (nb4 + j) * 8 + lc * 2;
            *(float2*)&s_S[(m0 + lr)     * 68 + col] = make_float2(acc[j][0], acc[j][1]);
            *(float2*)&s_S[(m0 + lr + 8) * 68 + col] = make_float2(acc[j][2], acc[j][3]);
        }
    }
    __syncthreads();

    // ---- P4: softmax rows of S; global attn fp32, smem tf32 ----
    {
        const int r = tid >> 2, s3 = tid & 3;
        float* row = s_S + r * 68 + s3 * 16;
        float4 v0 = *(float4*)&row[0], v1 = *(float4*)&row[4];
        float4 v2 = *(float4*)&row[8], v3 = *(float4*)&row[12];
        float mx = fmaxf(fmaxf(fmaxf(v0.x, v0.y), fmaxf(v0.z, v0.w)),
                         fmaxf(fmaxf(v1.x, v1.y), fmaxf(v1.z, v1.w)));
        mx = fmaxf(mx, fmaxf(fmaxf(fmaxf(v2.x, v2.y), fmaxf(v2.z, v2.w)),
                             fmaxf(fmaxf(v3.x, v3.y), fmaxf(v3.z, v3.w))));
        mx = fmaxf(mx, __shfl_xor_sync(~0u, mx, 1));
        mx = fmaxf(mx, __shfl_xor_sync(~0u, mx, 2));
        float e[16];
        e[0]=__expf(v0.x-mx); e[1]=__expf(v0.y-mx); e[2]=__expf(v0.z-mx); e[3]=__expf(v0.w-mx);
        e[4]=__expf(v1.x-mx); e[5]=__expf(v1.y-mx); e[6]=__expf(v1.z-mx); e[7]=__expf(v1.w-mx);
        e[8]=__expf(v2.x-mx); e[9]=__expf(v2.y-mx); e[10]=__expf(v2.z-mx); e[11]=__expf(v2.w-mx);
        e[12]=__expf(v3.x-mx); e[13]=__expf(v3.y-mx); e[14]=__expf(v3.z-mx); e[15]=__expf(v3.w-mx);
        float ssum = 0.f;
        #pragma unroll
        for (int i = 0; i < 16; i++) ssum += e[i];
        ssum += __shfl_xor_sync(~0u, ssum, 1);
        ssum += __shfl_xor_sync(~0u, ssum, 2);
        const float inv = 1.f / ssum;
        float* gattn = attn_out + (((size_t)(b * Hc + h) * Nc + r) * Nc) + s3 * 16;
        #pragma unroll
        for (int u = 0; u < 4; u++) {
            float p0 = e[4*u] * inv, p1 = e[4*u+1] * inv,
                  p2 = e[4*u+2] * inv, p3 = e[4*u+3] * inv;
            *(float4*)&gattn[4 * u] = make_float4(p0, p1, p2, p3);
            *(float4*)&row[4 * u]   = make_float4(tf32r(p0), tf32r(p1), tf32r(p2), tf32r(p3));
        }
    }
    __syncthreads();

    // ---- P5: out[q][p] = sum_n attn[q][n] * vT[p][n] -> g_o ----
    {
        float acc[4][4] = {};
        #pragma unroll
        for (int k8 = 0; k8 < 8; k8++) {
            const int k0 = k8 * 8;
            uint32_t a[4];
            a[0] = __float_as_uint(s_S[(m0 + lr)     * 68 + k0 + lc]);
            a[1] = __float_as_uint(s_S[(m0 + lr + 8) * 68 + k0 + lc]);
            a[2] = __float_as_uint(s_S[(m0 + lr)     * 68 + k0 + lc + 4]);
            a[3] = __float_as_uint(s_S[(m0 + lr + 8) * 68 + k0 + lc + 4]);
            #pragma unroll
            for (int j = 0; j < 4; j++) {
                const int pp = (nb4 + j) * 8;
                uint32_t bfr[2];
                bfr[0] = __float_as_uint(s_vT[(pp + lr) * 68 + k0 + lc]);
                bfr[1] = __float_as_uint(s_vT[(pp + lr) * 68 + k0 + lc + 4]);
                mma16n8k8(acc[j], a, bfr);
            }
        }
        float* ob = g_o + ((size_t)b * Nc) * 512 + h * 64;
        #pragma unroll
        for (int j = 0; j < 4; j++) {
            const int p = (nb4 + j) * 8 + lc * 2;
            *(float2*)(ob + (size_t)(m0 + lr) * 512 + p)     = make_float2(acc[j][0], acc[j][1]);
            *(float2*)(ob + (size_t)(m0 + lr + 8) * 512 + p) = make_float2(acc[j][2], acc[j][3]);
        }
    }
}

// ---------------------------------------------------------------------------
// Kernel 3: per-batch FC via mma.sync tf32 (unchanged R4).
// ---------------------------------------------------------------------------
static constexpr int SMEM3 = (64 * 132 * 2) * 4;

__global__ __launch_bounds__(256) void fc_mma(
    const float* __restrict__ Wfc, float* __restrict__ out)
{
    extern __shared__ float sm[];
    float* s_A = sm;
    float* s_W = sm + 64 * 132;

    const int b = blockIdx.x, tid = threadIdx.x;
    const int wid = tid >> 5, lane = tid & 31;
    const int lr = lane >> 2, lc = lane & 3;
    const float* A = g_o + (size_t)b * Nc * 512;

    const int m0 = (wid >> 1) * 16;
    const int n0 = (wid & 1) * 32;

    float acc[4][4] = {};

    for (int kc = 0; kc < 4; kc++) {
        __syncthreads();
        for (int i = tid; i < 2048; i += 256) {
            const int r = i >> 5, k4 = i & 31;
            float4 v = *(const float4*)(A + r * 512 + kc * 128 + k4 * 4);
            v.x = tf32r(v.x); v.y = tf32r(v.y); v.z = tf32r(v.z); v.w = tf32r(v.w);
            *(float4*)&s_A[r * 132 + k4 * 4] = v;
        }
        for (int i = tid; i < 2048; i += 256) {
            const int r = i >> 5, k4 = i & 31;
            float4 v = *(const float4*)(Wfc + r * 512 + kc * 128 + k4 * 4);
            v.x = tf32r(v.x); v.y = tf32r(v.y); v.z = tf32r(v.z); v.w = tf32r(v.w);
            *(float4*)&s_W[r * 132 + k4 * 4] = v;
        }
        __syncthreads();

        #pragma unroll
        for (int k8 = 0; k8 < 16; k8++) {
            const int k0 = k8 * 8;
            uint32_t a[4];
            a[0] = __float_as_uint(s_A[(m0 + lr)     * 132 + k0 + lc]);
            a[1] = __float_as_uint(s_A[(m0 + lr + 8) * 132 + k0 + lc]);
            a[2] = __float_as_uint(s_A[(m0 + lr)     * 132 + k0 + lc + 4]);
            a[3] = __float_as_uint(s_A[(m0 + lr + 8) * 132 + k0 + lc + 4]);
            #pragma unroll
            for (int t = 0; t < 4; t++) {
                uint32_t bfr[2];
                bfr[0] = __float_as_uint(s_W[(n0 + t * 8 + lr) * 132 + k0 + lc]);
                bfr[1] = __float_as_uint(s_W[(n0 + t * 8 + lr) * 132 + k0 + lc + 4]);
                mma16n8k8(acc[t], a, bfr);
            }
        }
    }
    float* ob = out + (size_t)b * 4096;
    #pragma unroll
    for (int t = 0; t < 4; t++) {
        const int o = n0 + t * 8 + lc * 2;
        *(float2*)(ob + (m0 + lr) * 64 + o)     = make_float2(acc[t][0], acc[t][1]);
        *(float2*)(ob + (m0 + lr + 8) * 64 + o) = make_float2(acc[t][2], acc[t][3]);
    }
}

// ---------------------------------------------------------------------------
extern "C" void kernel_launch(void* const* d_in, const int* in_sizes, int n_in,
                              void* d_out, int out_size) {
    const float* feat  = (const float*)d_in[0];
    const int*   sidx  = (const int*)  d_in[1];
    const float* gamma = (const float*)d_in[2];
    const float* beta  = (const float*)d_in[3];
    const float* Wq    = (const float*)d_in[4];
    const float* Wk    = (const float*)d_in[5];
    const float* Wv1   = (const float*)d_in[6];
    const float* Wv2   = (const float*)d_in[7];
    const float* Wfc   = (const float*)d_in[8];

    float* out  = (float*)d_out;
    float* attn = out + (size_t)Bc * Nc * 64;

    cudaFuncSetAttribute(ln_q_mma, cudaFuncAttributeMaxDynamicSharedMemorySize, SMEM1);
    cudaFuncSetAttribute(head_mma, cudaFuncAttributeMaxDynamicSharedMemorySize, SMEM2);
    cudaFuncSetAttribute(fc_mma,   cudaFuncAttributeMaxDynamicSharedMemorySize, SMEM3);

    ln_q_mma<<<Bc, 256, SMEM1>>>(feat, gamma, beta, Wq);
    head_mma<<<dim3(Hc, Bc), 256, SMEM2>>>(feat, sidx, Wk, Wv1, Wv2, attn);
    fc_mma<<<Bc, 256, SMEM3>>>(Wfc, out);
}

// round 6
// speedup vs baseline: 2.4111x; 1.0515x over previous
#include <cuda_runtime.h>
#include <math.h>
#include <stdint.h>

#define Bc 512
#define Mc 4096
#define Nc 64
#define Hc 8

// Scratch (device globals, allocation-free rule)
__device__ float g_y[(size_t)Bc * Mc];              // 8 MB, LN'd features (tf32, affine)
__device__ float g_o[(size_t)Bc * Nc * 512];        // 64 MB, (b,n, h*64+p)

__device__ __forceinline__ float tf32r(float x) {
    float r; asm("cvt.rna.tf32.f32 %0, %1;" : "=f"(r) : "f"(x)); return r;
}
__device__ __forceinline__ void mma16n8k8(float* c, const uint32_t* a, const uint32_t* b) {
    asm volatile(
        "mma.sync.aligned.m16n8k8.row.col.f32.tf32.tf32.f32 "
        "{%0,%1,%2,%3}, {%4,%5,%6,%7}, {%8,%9}, {%0,%1,%2,%3};"
        : "+f"(c[0]), "+f"(c[1]), "+f"(c[2]), "+f"(c[3])
        : "r"(a[0]), "r"(a[1]), "r"(a[2]), "r"(a[3]), "r"(b[0]), "r"(b[1]));
}

// ---------------------------------------------------------------------------
// Kernel 0: LayerNorm only -> g_y (tf32, gamma/beta applied). grid=B, 256 thr.
// ---------------------------------------------------------------------------
static constexpr int SMEMY = 4096 * 4 + 80;

__global__ __launch_bounds__(256) void ln_y_kernel(
    const float* __restrict__ feat, const float* __restrict__ gamma,
    const float* __restrict__ beta)
{
    extern __shared__ float sm[];
    float* s_x = sm;             // 4096
    float* s_red = sm + 4096;    // 18

    const int b = blockIdx.x, tid = threadIdx.x;
    const int wid = tid >> 5, lane = tid & 31;
    const float4* x4 = (const float4*)(feat + (size_t)b * Mc);

    float sum = 0.f, sq = 0.f;
    for (int i = tid; i < 1024; i += 256) {
        float4 v = x4[i];
        *(float4*)&s_x[i * 4] = v;
        sum += v.x + v.y + v.z + v.w;
        sq  += v.x*v.x + v.y*v.y + v.z*v.z + v.w*v.w;
    }
    #pragma unroll
    for (int o = 16; o; o >>= 1) {
        sum += __shfl_xor_sync(~0u, sum, o);
        sq  += __shfl_xor_sync(~0u, sq,  o);
    }
    if (lane == 0) { s_red[wid] = sum; s_red[wid + 8] = sq; }
    __syncthreads();
    if (tid == 0) {
        float S = 0.f, Q = 0.f;
        #pragma unroll
        for (int i = 0; i < 8; i++) { S += s_red[i]; Q += s_red[i + 8]; }
        float mu = S * (1.f / Mc);
        s_red[16] = mu;
        s_red[17] = rsqrtf(Q * (1.f / Mc) - mu * mu + 1e-5f);
    }
    __syncthreads();
    const float mu = s_red[16], rstd = s_red[17];
    float4* y4 = (float4*)(g_y + (size_t)b * Mc);
    const float4* g4 = (const float4*)gamma;
    const float4* b4 = (const float4*)beta;
    for (int i = tid; i < 1024; i += 256) {
        float4 v = *(float4*)&s_x[i * 4];
        float4 g = g4[i], bb = b4[i], y;
        y.x = tf32r((v.x - mu) * rstd * g.x + bb.x);
        y.y = tf32r((v.y - mu) * rstd * g.y + bb.y);
        y.z = tf32r((v.z - mu) * rstd * g.z + bb.z);
        y.w = tf32r((v.w - mu) * rstd * g.w + bb.w);
        y4[i] = y;
    }
}

// ---------------------------------------------------------------------------
// Kernel 1: per-(b,h) head; q projection fused (mma), key/S/AV on mma tf32.
// smem (floats): @0 kf[64][68] (first y[64][68], then S overlay)
//   | @4352 vT[64][68] (first feat[4096]) | @8704 keyT[64][36] (first wq[32][68])
//   | @11008 q[64][36] | @13312 wk[32][68] | @15488 wv[16].  62 KB, 3 CTA/SM.
// ---------------------------------------------------------------------------
static constexpr int SMEM2 = 15504 * 4;

__global__ __launch_bounds__(256) void head_mma(
    const float* __restrict__ feat, const int* __restrict__ sidx,
    const float* __restrict__ Wk, const float* __restrict__ Wv1,
    const float* __restrict__ Wv2, const float* __restrict__ Wq,
    float* __restrict__ attn_out)
{
    extern __shared__ float sm[];
    float* s_kf   = sm;            // [64][68] gathered features
    float* s_y    = sm;            // y overlay (before gather)
    float* s_S    = sm;            // S overlay (after P3)
    float* s_vT   = sm + 4352;     // [p][n] pitch 68
    float* s_feat = sm + 4352;     // 4096, dead after gather
    float* s_keyT = sm + 8704;     // [n][d] pitch 36
    float* s_wq   = sm + 8704;     // wq overlay (before keyT written)
    float* s_q    = sm + 11008;    // [q][d] pitch 36
    float* s_wk   = sm + 13312;    // [d][k] pitch 68
    float* s_wv   = sm + 15488;    // wv1[12], wv2[4]

    const int h = blockIdx.x, b = blockIdx.y, tid = threadIdx.x;
    const int wid = tid >> 5, lane = tid & 31;
    const int lr = lane >> 2, lc = lane & 3;
    const int* idx = sidx + (size_t)h * Mc;

    // ---- P0: stage feat, y (pitched), wq (x 1/64), wk, wv ----
    {
        const float4* xr = (const float4*)(feat + (size_t)b * Mc);
        float4* fr = (float4*)s_feat;
        for (int i = tid; i < 1024; i += 256) fr[i] = xr[i];
        const float* yg = g_y + (size_t)b * Mc;
        for (int i = tid; i < 4096; i += 256)
            s_y[(i >> 6) * 68 + (i & 63)] = yg[i];
        for (int i = tid; i < 2048; i += 256)
            s_wq[(i >> 6) * 68 + (i & 63)] = tf32r(Wq[(h * 32 + (i >> 6)) * 64 + (i & 63)]) * 0.015625f;
        for (int i = tid; i < 2048; i += 256)
            s_wk[(i >> 6) * 68 + (i & 63)] = tf32r(Wk[h * 2048 + i]);
        if (tid < 12) s_wv[tid] = Wv1[h * 12 + tid];
        if (tid >= 32 && tid < 36) s_wv[12 + tid - 32] = Wv2[h * 4 + tid - 32];
    }
    __syncthreads();

    // ---- P0b: q GEMM  q[n][d] = sum_k y[n][k] * wq[d][k]  (M=64,N=32,K=64) ----
    {
        const int qm = (wid & 3) * 16;
        const int qd = (wid >> 2) * 16;      // 2 d8-tiles: qd, qd+8
        float acc[2][4] = {};
        #pragma unroll
        for (int k8 = 0; k8 < 8; k8++) {
            const int k0 = k8 * 8;
            uint32_t a[4];
            a[0] = __float_as_uint(s_y[(qm + lr)     * 68 + k0 + lc]);
            a[1] = __float_as_uint(s_y[(qm + lr + 8) * 68 + k0 + lc]);
            a[2] = __float_as_uint(s_y[(qm + lr)     * 68 + k0 + lc + 4]);
            a[3] = __float_as_uint(s_y[(qm + lr + 8) * 68 + k0 + lc + 4]);
            #pragma unroll
            for (int t = 0; t < 2; t++) {
                uint32_t bfr[2];
                bfr[0] = __float_as_uint(s_wq[(qd + t * 8 + lr) * 68 + k0 + lc]);
                bfr[1] = __float_as_uint(s_wq[(qd + t * 8 + lr) * 68 + k0 + lc + 4]);
                mma16n8k8(acc[t], a, bfr);
            }
        }
        __syncthreads();   // all reads of y/wq complete before overwrite
        #pragma unroll
        for (int t = 0; t < 2; t++) {
            const int d = qd + t * 8 + lc * 2;
            s_q[(qm + lr) * 36 + d]         = tf32r(acc[t][0]);
            s_q[(qm + lr) * 36 + d + 1]     = tf32r(acc[t][1]);
            s_q[(qm + lr + 8) * 36 + d]     = tf32r(acc[t][2]);
            s_q[(qm + lr + 8) * 36 + d + 1] = tf32r(acc[t][3]);
        }
    }

    // ---- P1: gather kf from smem feat (overwrites y); zero conv pad ----
    for (int i = tid; i < 4096; i += 256)
        s_kf[(i >> 6) * 68 + (i & 63)] = s_feat[idx[i]];
    if (tid < 128) s_kf[(tid >> 1) * 68 + 64 + (tid & 1)] = 0.f;
    __syncthreads();

    // ---- P2a: key GEMM  keyT[n][d] = sum_k kf[n][k] * wk[d][k] ----
    {
        const int m0 = (wid & 1) * 16;        // d tile
        const int nb = (wid >> 1) * 8;        // ntiles {nb, nb+32}
        float acc[2][4] = {};
        #pragma unroll
        for (int k8 = 0; k8 < 8; k8++) {
            const int k0 = k8 * 8;
            uint32_t a[4];
            a[0] = __float_as_uint(s_wk[(m0 + lr)     * 68 + k0 + lc]);
            a[1] = __float_as_uint(s_wk[(m0 + lr + 8) * 68 + k0 + lc]);
            a[2] = __float_as_uint(s_wk[(m0 + lr)     * 68 + k0 + lc + 4]);
            a[3] = __float_as_uint(s_wk[(m0 + lr + 8) * 68 + k0 + lc + 4]);
            #pragma unroll
            for (int t = 0; t < 2; t++) {
                const int nn = nb + t * 32;
                uint32_t bfr[2];
                bfr[0] = __float_as_uint(tf32r(s_kf[(nn + lr) * 68 + k0 + lc]));
                bfr[1] = __float_as_uint(tf32r(s_kf[(nn + lr) * 68 + k0 + lc + 4]));
                mma16n8k8(acc[t], a, bfr);
            }
        }
        #pragma unroll
        for (int t = 0; t < 2; t++) {
            const int n = nb + t * 32 + lc * 2, d = m0 + lr;
            s_keyT[n * 36 + d]           = tf32r(acc[t][0]);
            s_keyT[(n + 1) * 36 + d]     = tf32r(acc[t][1]);
            s_keyT[n * 36 + d + 8]       = tf32r(acc[t][2]);
            s_keyT[(n + 1) * 36 + d + 8] = tf32r(acc[t][3]);
        }
    }
    // ---- P2b: conv -> vT[p][n] = tf32(kf[n][p] + sum_d relu(conv3)*wv2) ----
    {
        const int n = tid >> 2, p0 = (tid & 3) * 16;
        const float* kr = s_kf + n * 68;
        float w0[4], w1[4], w2[4], w3[4];
        #pragma unroll
        for (int d = 0; d < 4; d++) {
            w0[d] = s_wv[d * 3]; w1[d] = s_wv[d * 3 + 1];
            w2[d] = s_wv[d * 3 + 2]; w3[d] = s_wv[12 + d];
        }
        float x0 = kr[p0], x1 = kr[p0 + 1];
        #pragma unroll
        for (int i = 0; i < 16; i++) {
            float x2 = kr[p0 + i + 2];
            float acc = x0;
            #pragma unroll
            for (int d = 0; d < 4; d++)
                acc += fmaxf(x0 * w0[d] + x1 * w1[d] + x2 * w2[d], 0.f) * w3[d];
            s_vT[(p0 + i) * 68 + n] = tf32r(acc);
            x0 = x1; x1 = x2;
        }
    }
    __syncthreads();

    const int m0 = (wid >> 1) * 16;       // q tile
    const int nb4 = (wid & 1) * 4;        // 4 n-tiles

    // ---- P3: S[q][n] = sum_d q[q][d] * keyT[n][d]  (kf dead -> S overlay) ----
    {
        float acc[4][4] = {};
        #pragma unroll
        for (int k8 = 0; k8 < 4; k8++) {
            const int k0 = k8 * 8;
            uint32_t a[4];
            a[0] = __float_as_uint(s_q[(m0 + lr)     * 36 + k0 + lc]);
            a[1] = __float_as_uint(s_q[(m0 + lr + 8) * 36 + k0 + lc]);
            a[2] = __float_as_uint(s_q[(m0 + lr)     * 36 + k0 + lc + 4]);
            a[3] = __float_as_uint(s_q[(m0 + lr + 8) * 36 + k0 + lc + 4]);
            #pragma unroll
            for (int j = 0; j < 4; j++) {
                const int nn = (nb4 + j) * 8;
                uint32_t bfr[2];
                bfr[0] = __float_as_uint(s_keyT[(nn + lr) * 36 + k0 + lc]);
                bfr[1] = __float_as_uint(s_keyT[(nn + lr) * 36 + k0 + lc + 4]);
                mma16n8k8(acc[j], a, bfr);
            }
        }
        #pragma unroll
        for (int j = 0; j < 4; j++) {
            const int col = (nb4 + j) * 8 + lc * 2;
            *(float2*)&s_S[(m0 + lr)     * 68 + col] = make_float2(acc[j][0], acc[j][1]);
            *(float2*)&s_S[(m0 + lr + 8) * 68 + col] = make_float2(acc[j][2], acc[j][3]);
        }
    }
    __syncthreads();

    // ---- P4: softmax rows of S; global attn fp32, smem tf32 ----
    {
        const int r = tid >> 2, s3 = tid & 3;
        float* row = s_S + r * 68 + s3 * 16;
        float4 v0 = *(float4*)&row[0], v1 = *(float4*)&row[4];
        float4 v2 = *(float4*)&row[8], v3 = *(float4*)&row[12];
        float mx = fmaxf(fmaxf(fmaxf(v0.x, v0.y), fmaxf(v0.z, v0.w)),
                         fmaxf(fmaxf(v1.x, v1.y), fmaxf(v1.z, v1.w)));
        mx = fmaxf(mx, fmaxf(fmaxf(fmaxf(v2.x, v2.y), fmaxf(v2.z, v2.w)),
                             fmaxf(fmaxf(v3.x, v3.y), fmaxf(v3.z, v3.w))));
        mx = fmaxf(mx, __shfl_xor_sync(~0u, mx, 1));
        mx = fmaxf(mx, __shfl_xor_sync(~0u, mx, 2));
        float e[16];
        e[0]=__expf(v0.x-mx); e[1]=__expf(v0.y-mx); e[2]=__expf(v0.z-mx); e[3]=__expf(v0.w-mx);
        e[4]=__expf(v1.x-mx); e[5]=__expf(v1.y-mx); e[6]=__expf(v1.z-mx); e[7]=__expf(v1.w-mx);
        e[8]=__expf(v2.x-mx); e[9]=__expf(v2.y-mx); e[10]=__expf(v2.z-mx); e[11]=__expf(v2.w-mx);
        e[12]=__expf(v3.x-mx); e[13]=__expf(v3.y-mx); e[14]=__expf(v3.z-mx); e[15]=__expf(v3.w-mx);
        float ssum = 0.f;
        #pragma unroll
        for (int i = 0; i < 16; i++) ssum += e[i];
        ssum += __shfl_xor_sync(~0u, ssum, 1);
        ssum += __shfl_xor_sync(~0u, ssum, 2);
        const float inv = 1.f / ssum;
        float* gattn = attn_out + (((size_t)(b * Hc + h) * Nc + r) * Nc) + s3 * 16;
        #pragma unroll
        for (int u = 0; u < 4; u++) {
            float p0 = e[4*u] * inv, p1 = e[4*u+1] * inv,
                  p2 = e[4*u+2] * inv, p3 = e[4*u+3] * inv;
            *(float4*)&gattn[4 * u] = make_float4(p0, p1, p2, p3);
            *(float4*)&row[4 * u]   = make_float4(tf32r(p0), tf32r(p1), tf32r(p2), tf32r(p3));
        }
    }
    __syncthreads();

    // ---- P5: out[q][p] = sum_n attn[q][n] * vT[p][n] -> g_o ----
    {
        float acc[4][4] = {};
        #pragma unroll
        for (int k8 = 0; k8 < 8; k8++) {
            const int k0 = k8 * 8;
            uint32_t a[4];
            a[0] = __float_as_uint(s_S[(m0 + lr)     * 68 + k0 + lc]);
            a[1] = __float_as_uint(s_S[(m0 + lr + 8) * 68 + k0 + lc]);
            a[2] = __float_as_uint(s_S[(m0 + lr)     * 68 + k0 + lc + 4]);
            a[3] = __float_as_uint(s_S[(m0 + lr + 8) * 68 + k0 + lc + 4]);
            #pragma unroll
            for (int j = 0; j < 4; j++) {
                const int pp = (nb4 + j) * 8;
                uint32_t bfr[2];
                bfr[0] = __float_as_uint(s_vT[(pp + lr) * 68 + k0 + lc]);
                bfr[1] = __float_as_uint(s_vT[(pp + lr) * 68 + k0 + lc + 4]);
                mma16n8k8(acc[j], a, bfr);
            }
        }
        float* ob = g_o + ((size_t)b * Nc) * 512 + h * 64;
        #pragma unroll
        for (int j = 0; j < 4; j++) {
            const int p = (nb4 + j) * 8 + lc * 2;
            *(float2*)(ob + (size_t)(m0 + lr) * 512 + p)     = make_float2(acc[j][0], acc[j][1]);
            *(float2*)(ob + (size_t)(m0 + lr + 8) * 512 + p) = make_float2(acc[j][2], acc[j][3]);
        }
    }
}

// ---------------------------------------------------------------------------
// Kernel 2: per-batch FC via mma.sync tf32 (unchanged, proven).
// ---------------------------------------------------------------------------
static constexpr int SMEM3 = (64 * 132 * 2) * 4;

__global__ __launch_bounds__(256) void fc_mma(
    const float* __restrict__ Wfc, float* __restrict__ out)
{
    extern __shared__ float sm[];
    float* s_A = sm;
    float* s_W = sm + 64 * 132;

    const int b = blockIdx.x, tid = threadIdx.x;
    const int wid = tid >> 5, lane = tid & 31;
    const int lr = lane >> 2, lc = lane & 3;
    const float* A = g_o + (size_t)b * Nc * 512;

    const int m0 = (wid >> 1) * 16;
    const int n0 = (wid & 1) * 32;

    float acc[4][4] = {};

    for (int kc = 0; kc < 4; kc++) {
        __syncthreads();
        for (int i = tid; i < 2048; i += 256) {
            const int r = i >> 5, k4 = i & 31;
            float4 v = *(const float4*)(A + r * 512 + kc * 128 + k4 * 4);
            v.x = tf32r(v.x); v.y = tf32r(v.y); v.z = tf32r(v.z); v.w = tf32r(v.w);
            *(float4*)&s_A[r * 132 + k4 * 4] = v;
        }
        for (int i = tid; i < 2048; i += 256) {
            const int r = i >> 5, k4 = i & 31;
            float4 v = *(const float4*)(Wfc + r * 512 + kc * 128 + k4 * 4);
            v.x = tf32r(v.x); v.y = tf32r(v.y); v.z = tf32r(v.z); v.w = tf32r(v.w);
            *(float4*)&s_W[r * 132 + k4 * 4] = v;
        }
        __syncthreads();

        #pragma unroll
        for (int k8 = 0; k8 < 16; k8++) {
            const int k0 = k8 * 8;
            uint32_t a[4];
            a[0] = __float_as_uint(s_A[(m0 + lr)     * 132 + k0 + lc]);
            a[1] = __float_as_uint(s_A[(m0 + lr + 8) * 132 + k0 + lc]);
            a[2] = __float_as_uint(s_A[(m0 + lr)     * 132 + k0 + lc + 4]);
            a[3] = __float_as_uint(s_A[(m0 + lr + 8) * 132 + k0 + lc + 4]);
            #pragma unroll
            for (int t = 0; t < 4; t++) {
                uint32_t bfr[2];
                bfr[0] = __float_as_uint(s_W[(n0 + t * 8 + lr) * 132 + k0 + lc]);
                bfr[1] = __float_as_uint(s_W[(n0 + t * 8 + lr) * 132 + k0 + lc + 4]);
                mma16n8k8(acc[t], a, bfr);
            }
        }
    }
    float* ob = out + (size_t)b * 4096;
    #pragma unroll
    for (int t = 0; t < 4; t++) {
        const int o = n0 + t * 8 + lc * 2;
        *(float2*)(ob + (m0 + lr) * 64 + o)     = make_float2(acc[t][0], acc[t][1]);
        *(float2*)(ob + (m0 + lr + 8) * 64 + o) = make_float2(acc[t][2], acc[t][3]);
    }
}

// ---------------------------------------------------------------------------
extern "C" void kernel_launch(void* const* d_in, const int* in_sizes, int n_in,
                              void* d_out, int out_size) {
    const float* feat  = (const float*)d_in[0];
    const int*   sidx  = (const int*)  d_in[1];
    const float* gamma = (const float*)d_in[2];
    const float* beta  = (const float*)d_in[3];
    const float* Wq    = (const float*)d_in[4];
    const float* Wk    = (const float*)d_in[5];
    const float* Wv1   = (const float*)d_in[6];
    const float* Wv2   = (const float*)d_in[7];
    const float* Wfc   = (const float*)d_in[8];

    float* out  = (float*)d_out;
    float* attn = out + (size_t)Bc * Nc * 64;

    cudaFuncSetAttribute(ln_y_kernel, cudaFuncAttributeMaxDynamicSharedMemorySize, SMEMY);
    cudaFuncSetAttribute(head_mma,    cudaFuncAttributeMaxDynamicSharedMemorySize, SMEM2);
    cudaFuncSetAttribute(fc_mma,      cudaFuncAttributeMaxDynamicSharedMemorySize, SMEM3);

    ln_y_kernel<<<Bc, 256, SMEMY>>>(feat, gamma, beta);
    head_mma<<<dim3(Hc, Bc), 256, SMEM2>>>(feat, sidx, Wk, Wv1, Wv2, Wq, attn);
    fc_mma<<<Bc, 256, SMEM3>>>(Wfc, out);
}

// round 7
// speedup vs baseline: 3.7032x; 1.5359x over previous
#include <cuda_runtime.h>
#include <math.h>
#include <stdint.h>

#define Bc 512
#define Mc 4096
#define Nc 64
#define Hc 8

// Scratch (device globals, allocation-free rule)
__device__ float g_y[(size_t)Bc * Mc];              // 8 MB, LN'd features (tf32, affine)
__device__ float g_o[(size_t)Bc * Nc * 512];        // 64 MB, (b,n, h*64+p)

__device__ __forceinline__ float tf32r(float x) {
    float r; asm("cvt.rna.tf32.f32 %0, %1;" : "=f"(r) : "f"(x)); return r;
}
__device__ __forceinline__ void mma16n8k8(float* c, const uint32_t* a, const uint32_t* b) {
    asm volatile(
        "mma.sync.aligned.m16n8k8.row.col.f32.tf32.tf32.f32 "
        "{%0,%1,%2,%3}, {%4,%5,%6,%7}, {%8,%9}, {%0,%1,%2,%3};"
        : "+f"(c[0]), "+f"(c[1]), "+f"(c[2]), "+f"(c[3])
        : "r"(a[0]), "r"(a[1]), "r"(a[2]), "r"(a[3]), "r"(b[0]), "r"(b[1]));
}
__device__ __forceinline__ uint32_t smem_u32(const void* p) {
    uint32_t a;
    asm("{ .reg .u64 t; cvta.to.shared.u64 t, %1; cvt.u32.u64 %0, t; }" : "=r"(a) : "l"(p));
    return a;
}
__device__ __forceinline__ void cp16(uint32_t s, const void* g) {
    asm volatile("cp.async.cg.shared.global [%0], [%1], 16;" :: "r"(s), "l"(g));
}
#define CP_COMMIT()  asm volatile("cp.async.commit_group;" ::: "memory")
#define CP_WAIT(n)   asm volatile("cp.async.wait_group %0;" :: "n"(n) : "memory")

// ---------------------------------------------------------------------------
// Kernel 0: LayerNorm only -> g_y (tf32, gamma/beta applied). grid=B, 256 thr.
// ---------------------------------------------------------------------------
static constexpr int SMEMY = 4096 * 4 + 80;

__global__ __launch_bounds__(256) void ln_y_kernel(
    const float* __restrict__ feat, const float* __restrict__ gamma,
    const float* __restrict__ beta)
{
    extern __shared__ float sm[];
    float* s_x = sm;             // 4096
    float* s_red = sm + 4096;    // 18

    const int b = blockIdx.x, tid = threadIdx.x;
    const int wid = tid >> 5, lane = tid & 31;
    const float4* x4 = (const float4*)(feat + (size_t)b * Mc);

    float sum = 0.f, sq = 0.f;
    for (int i = tid; i < 1024; i += 256) {
        float4 v = x4[i];
        *(float4*)&s_x[i * 4] = v;
        sum += v.x + v.y + v.z + v.w;
        sq  += v.x*v.x + v.y*v.y + v.z*v.z + v.w*v.w;
    }
    #pragma unroll
    for (int o = 16; o; o >>= 1) {
        sum += __shfl_xor_sync(~0u, sum, o);
        sq  += __shfl_xor_sync(~0u, sq,  o);
    }
    if (lane == 0) { s_red[wid] = sum; s_red[wid + 8] = sq; }
    __syncthreads();
    if (tid == 0) {
        float S = 0.f, Q = 0.f;
        #pragma unroll
        for (int i = 0; i < 8; i++) { S += s_red[i]; Q += s_red[i + 8]; }
        float mu = S * (1.f / Mc);
        s_red[16] = mu;
        s_red[17] = rsqrtf(Q * (1.f / Mc) - mu * mu + 1e-5f);
    }
    __syncthreads();
    const float mu = s_red[16], rstd = s_red[17];
    float4* y4 = (float4*)(g_y + (size_t)b * Mc);
    const float4* g4 = (const float4*)gamma;
    const float4* b4 = (const float4*)beta;
    for (int i = tid; i < 1024; i += 256) {
        float4 v = *(float4*)&s_x[i * 4];
        float4 g = g4[i], bb = b4[i], y;
        y.x = tf32r((v.x - mu) * rstd * g.x + bb.x);
        y.y = tf32r((v.y - mu) * rstd * g.y + bb.y);
        y.z = tf32r((v.z - mu) * rstd * g.z + bb.z);
        y.w = tf32r((v.w - mu) * rstd * g.w + bb.w);
        y4[i] = y;
    }
}

// ---------------------------------------------------------------------------
// Kernel 1: per-(b,h) head; q projection fused (mma), key/S/AV on mma tf32.
// smem (floats): @0 kf[64][68] (first y[64][68], then S overlay)
//   | @4352 vT[64][68] (first feat[4096]) | @8704 keyT[64][36] (first wq[32][68])
//   | @11008 q[64][36] | @13312 wk[32][68] | @15488 wv[16].  62 KB, 3 CTA/SM.
// ---------------------------------------------------------------------------
static constexpr int SMEM2 = 15504 * 4;

__global__ __launch_bounds__(256) void head_mma(
    const float* __restrict__ feat, const int* __restrict__ sidx,
    const float* __restrict__ Wk, const float* __restrict__ Wv1,
    const float* __restrict__ Wv2, const float* __restrict__ Wq,
    float* __restrict__ attn_out)
{
    extern __shared__ float sm[];
    float* s_kf   = sm;            // [64][68] gathered features
    float* s_y    = sm;            // y overlay (before gather)
    float* s_S    = sm;            // S overlay (after P3)
    float* s_vT   = sm + 4352;     // [p][n] pitch 68
    float* s_feat = sm + 4352;     // 4096, dead after gather
    float* s_keyT = sm + 8704;     // [n][d] pitch 36
    float* s_wq   = sm + 8704;     // wq overlay (before keyT written)
    float* s_q    = sm + 11008;    // [q][d] pitch 36
    float* s_wk   = sm + 13312;    // [d][k] pitch 68
    float* s_wv   = sm + 15488;    // wv1[12], wv2[4]

    const int h = blockIdx.x, b = blockIdx.y, tid = threadIdx.x;
    const int wid = tid >> 5, lane = tid & 31;
    const int lr = lane >> 2, lc = lane & 3;
    const int* idx = sidx + (size_t)h * Mc;

    // ---- P0: stage feat, y (pitched), wq (x 1/64), wk, wv — all float4 ----
    {
        const float4* xr = (const float4*)(feat + (size_t)b * Mc);
        float4* fr = (float4*)s_feat;
        for (int i = tid; i < 1024; i += 256) fr[i] = xr[i];

        const float4* yg4 = (const float4*)(g_y + (size_t)b * Mc);
        #pragma unroll
        for (int j = 0; j < 4; j++) {
            int i = tid + j * 256;              // 0..1023
            int n = i >> 4, k4 = i & 15;
            *(float4*)&s_y[n * 68 + k4 * 4] = yg4[i];
        }
        {
            int i = tid & 255;
            if (i < 512) {
                int e = i >> 4, k4 = i & 15;
                float4 w = ((const float4*)(Wq + (h * 32 + e) * 64))[k4];
                w.x = tf32r(w.x) * 0.015625f; w.y = tf32r(w.y) * 0.015625f;
                w.z = tf32r(w.z) * 0.015625f; w.w = tf32r(w.w) * 0.015625f;
                *(float4*)&s_wq[e * 68 + k4 * 4] = w;
                i += 256;
                e = i >> 4; k4 = i & 15;
                float4 w2 = ((const float4*)(Wq + (h * 32 + e) * 64))[k4];
                w2.x = tf32r(w2.x) * 0.015625f; w2.y = tf32r(w2.y) * 0.015625f;
                w2.z = tf32r(w2.z) * 0.015625f; w2.w = tf32r(w2.w) * 0.015625f;
                *(float4*)&s_wq[e * 68 + k4 * 4] = w2;
            }
        }
        #pragma unroll
        for (int j = 0; j < 2; j++) {
            int i = tid + j * 256;              // 0..511
            int d = i >> 4, k4 = i & 15;
            float4 w = ((const float4*)(Wk + (h * 32 + d) * 64))[k4];
            w.x = tf32r(w.x); w.y = tf32r(w.y); w.z = tf32r(w.z); w.w = tf32r(w.w);
            *(float4*)&s_wk[d * 68 + k4 * 4] = w;
        }
        if (tid < 12) s_wv[tid] = Wv1[h * 12 + tid];
        if (tid >= 32 && tid < 36) s_wv[12 + tid - 32] = Wv2[h * 4 + tid - 32];
    }
    __syncthreads();

    // ---- P0b: q GEMM  q[n][d] = sum_k y[n][k] * wq[d][k]  (M=64,N=32,K=64) ----
    {
        const int qm = (wid & 3) * 16;
        const int qd = (wid >> 2) * 16;      // 2 d8-tiles: qd, qd+8
        float acc[2][4] = {};
        #pragma unroll
        for (int k8 = 0; k8 < 8; k8++) {
            const int k0 = k8 * 8;
            uint32_t a[4];
            a[0] = __float_as_uint(s_y[(qm + lr)     * 68 + k0 + lc]);
            a[1] = __float_as_uint(s_y[(qm + lr + 8) * 68 + k0 + lc]);
            a[2] = __float_as_uint(s_y[(qm + lr)     * 68 + k0 + lc + 4]);
            a[3] = __float_as_uint(s_y[(qm + lr + 8) * 68 + k0 + lc + 4]);
            #pragma unroll
            for (int t = 0; t < 2; t++) {
                uint32_t bfr[2];
                bfr[0] = __float_as_uint(s_wq[(qd + t * 8 + lr) * 68 + k0 + lc]);
                bfr[1] = __float_as_uint(s_wq[(qd + t * 8 + lr) * 68 + k0 + lc + 4]);
                mma16n8k8(acc[t], a, bfr);
            }
        }
        __syncthreads();   // all reads of y/wq complete before overwrite
        #pragma unroll
        for (int t = 0; t < 2; t++) {
            const int d = qd + t * 8 + lc * 2;
            s_q[(qm + lr) * 36 + d]         = tf32r(acc[t][0]);
            s_q[(qm + lr) * 36 + d + 1]     = tf32r(acc[t][1]);
            s_q[(qm + lr + 8) * 36 + d]     = tf32r(acc[t][2]);
            s_q[(qm + lr + 8) * 36 + d + 1] = tf32r(acc[t][3]);
        }
    }

    // ---- P1: gather kf from smem feat (int4 idx, float4 stores); conv pad ----
    {
        const int4* idx4 = (const int4*)idx;
        #pragma unroll
        for (int j = 0; j < 4; j++) {
            int i = tid + j * 256;              // 0..1023
            int4 v = idx4[i];
            int n = i >> 4, k = (i & 15) * 4;
            float4 g = make_float4(s_feat[v.x], s_feat[v.y], s_feat[v.z], s_feat[v.w]);
            *(float4*)&s_kf[n * 68 + k] = g;
        }
        if (tid < 128) s_kf[(tid >> 1) * 68 + 64 + (tid & 1)] = 0.f;
    }
    __syncthreads();

    // ---- P2a: key GEMM  keyT[n][d] = sum_k kf[n][k] * wk[d][k] ----
    {
        const int m0 = (wid & 1) * 16;        // d tile
        const int nb = (wid >> 1) * 8;        // ntiles {nb, nb+32}
        float acc[2][4] = {};
        #pragma unroll
        for (int k8 = 0; k8 < 8; k8++) {
            const int k0 = k8 * 8;
            uint32_t a[4];
            a[0] = __float_as_uint(s_wk[(m0 + lr)     * 68 + k0 + lc]);
            a[1] = __float_as_uint(s_wk[(m0 + lr + 8) * 68 + k0 + lc]);
            a[2] = __float_as_uint(s_wk[(m0 + lr)     * 68 + k0 + lc + 4]);
            a[3] = __float_as_uint(s_wk[(m0 + lr + 8) * 68 + k0 + lc + 4]);
            #pragma unroll
            for (int t = 0; t < 2; t++) {
                const int nn = nb + t * 32;
                uint32_t bfr[2];
                bfr[0] = __float_as_uint(tf32r(s_kf[(nn + lr) * 68 + k0 + lc]));
                bfr[1] = __float_as_uint(tf32r(s_kf[(nn + lr) * 68 + k0 + lc + 4]));
                mma16n8k8(acc[t], a, bfr);
            }
        }
        #pragma unroll
        for (int t = 0; t < 2; t++) {
            const int n = nb + t * 32 + lc * 2, d = m0 + lr;
            s_keyT[n * 36 + d]           = tf32r(acc[t][0]);
            s_keyT[(n + 1) * 36 + d]     = tf32r(acc[t][1]);
            s_keyT[n * 36 + d + 8]       = tf32r(acc[t][2]);
            s_keyT[(n + 1) * 36 + d + 8] = tf32r(acc[t][3]);
        }
    }
    // ---- P2b: conv -> vT[p][n] = tf32(kf[n][p] + sum_d relu(conv3)*wv2) ----
    {
        const int n = tid >> 2, p0 = (tid & 3) * 16;
        const float* kr = s_kf + n * 68;
        float w0[4], w1[4], w2[4], w3[4];
        #pragma unroll
        for (int d = 0; d < 4; d++) {
            w0[d] = s_wv[d * 3]; w1[d] = s_wv[d * 3 + 1];
            w2[d] = s_wv[d * 3 + 2]; w3[d] = s_wv[12 + d];
        }
        float x0 = kr[p0], x1 = kr[p0 + 1];
        #pragma unroll
        for (int i = 0; i < 16; i++) {
            float x2 = kr[p0 + i + 2];
            float acc = x0;
            #pragma unroll
            for (int d = 0; d < 4; d++)
                acc += fmaxf(x0 * w0[d] + x1 * w1[d] + x2 * w2[d], 0.f) * w3[d];
            s_vT[(p0 + i) * 68 + n] = tf32r(acc);
            x0 = x1; x1 = x2;
        }
    }
    __syncthreads();

    const int m0 = (wid >> 1) * 16;       // q tile
    const int nb4 = (wid & 1) * 4;        // 4 n-tiles

    // ---- P3: S[q][n] = sum_d q[q][d] * keyT[n][d]  (kf dead -> S overlay) ----
    {
        float acc[4][4] = {};
        #pragma unroll
        for (int k8 = 0; k8 < 4; k8++) {
            const int k0 = k8 * 8;
            uint32_t a[4];
            a[0] = __float_as_uint(s_q[(m0 + lr)     * 36 + k0 + lc]);
            a[1] = __float_as_uint(s_q[(m0 + lr + 8) * 36 + k0 + lc]);
            a[2] = __float_as_uint(s_q[(m0 + lr)     * 36 + k0 + lc + 4]);
            a[3] = __float_as_uint(s_q[(m0 + lr + 8) * 36 + k0 + lc + 4]);
            #pragma unroll
            for (int j = 0; j < 4; j++) {
                const int nn = (nb4 + j) * 8;
                uint32_t bfr[2];
                bfr[0] = __float_as_uint(s_keyT[(nn + lr) * 36 + k0 + lc]);
                bfr[1] = __float_as_uint(s_keyT[(nn + lr) * 36 + k0 + lc + 4]);
                mma16n8k8(acc[j], a, bfr);
            }
        }
        #pragma unroll
        for (int j = 0; j < 4; j++) {
            const int col = (nb4 + j) * 8 + lc * 2;
            *(float2*)&s_S[(m0 + lr)     * 68 + col] = make_float2(acc[j][0], acc[j][1]);
            *(float2*)&s_S[(m0 + lr + 8) * 68 + col] = make_float2(acc[j][2], acc[j][3]);
        }
    }
    __syncthreads();

    // ---- P4: softmax rows of S; global attn fp32, smem tf32 ----
    {
        const int r = tid >> 2, s3 = tid & 3;
        float* row = s_S + r * 68 + s3 * 16;
        float4 v0 = *(float4*)&row[0], v1 = *(float4*)&row[4];
        float4 v2 = *(float4*)&row[8], v3 = *(float4*)&row[12];
        float mx = fmaxf(fmaxf(fmaxf(v0.x, v0.y), fmaxf(v0.z, v0.w)),
                         fmaxf(fmaxf(v1.x, v1.y), fmaxf(v1.z, v1.w)));
        mx = fmaxf(mx, fmaxf(fmaxf(fmaxf(v2.x, v2.y), fmaxf(v2.z, v2.w)),
                             fmaxf(fmaxf(v3.x, v3.y), fmaxf(v3.z, v3.w))));
        mx = fmaxf(mx, __shfl_xor_sync(~0u, mx, 1));
        mx = fmaxf(mx, __shfl_xor_sync(~0u, mx, 2));
        float e[16];
        e[0]=__expf(v0.x-mx); e[1]=__expf(v0.y-mx); e[2]=__expf(v0.z-mx); e[3]=__expf(v0.w-mx);
        e[4]=__expf(v1.x-mx); e[5]=__expf(v1.y-mx); e[6]=__expf(v1.z-mx); e[7]=__expf(v1.w-mx);
        e[8]=__expf(v2.x-mx); e[9]=__expf(v2.y-mx); e[10]=__expf(v2.z-mx); e[11]=__expf(v2.w-mx);
        e[12]=__expf(v3.x-mx); e[13]=__expf(v3.y-mx); e[14]=__expf(v3.z-mx); e[15]=__expf(v3.w-mx);
        float ssum = 0.f;
        #pragma unroll
        for (int i = 0; i < 16; i++) ssum += e[i];
        ssum += __shfl_xor_sync(~0u, ssum, 1);
        ssum += __shfl_xor_sync(~0u, ssum, 2);
        const float inv = 1.f / ssum;
        float* gattn = attn_out + (((size_t)(b * Hc + h) * Nc + r) * Nc) + s3 * 16;
        #pragma unroll
        for (int u = 0; u < 4; u++) {
            float p0 = e[4*u] * inv, p1 = e[4*u+1] * inv,
                  p2 = e[4*u+2] * inv, p3 = e[4*u+3] * inv;
            *(float4*)&gattn[4 * u] = make_float4(p0, p1, p2, p3);
            *(float4*)&row[4 * u]   = make_float4(tf32r(p0), tf32r(p1), tf32r(p2), tf32r(p3));
        }
    }
    __syncthreads();

    // ---- P5: out[q][p] = sum_n attn[q][n] * vT[p][n] -> g_o ----
    {
        float acc[4][4] = {};
        #pragma unroll
        for (int k8 = 0; k8 < 8; k8++) {
            const int k0 = k8 * 8;
            uint32_t a[4];
            a[0] = __float_as_uint(s_S[(m0 + lr)     * 68 + k0 + lc]);
            a[1] = __float_as_uint(s_S[(m0 + lr + 8) * 68 + k0 + lc]);
            a[2] = __float_as_uint(s_S[(m0 + lr)     * 68 + k0 + lc + 4]);
            a[3] = __float_as_uint(s_S[(m0 + lr + 8) * 68 + k0 + lc + 4]);
            #pragma unroll
            for (int j = 0; j < 4; j++) {
                const int pp = (nb4 + j) * 8;
                uint32_t bfr[2];
                bfr[0] = __float_as_uint(s_vT[(pp + lr) * 68 + k0 + lc]);
                bfr[1] = __float_as_uint(s_vT[(pp + lr) * 68 + k0 + lc + 4]);
                mma16n8k8(acc[j], a, bfr);
            }
        }
        float* ob = g_o + ((size_t)b * Nc) * 512 + h * 64;
        #pragma unroll
        for (int j = 0; j < 4; j++) {
            const int p = (nb4 + j) * 8 + lc * 2;
            *(float2*)(ob + (size_t)(m0 + lr) * 512 + p)     = make_float2(acc[j][0], acc[j][1]);
            *(float2*)(ob + (size_t)(m0 + lr + 8) * 512 + p) = make_float2(acc[j][2], acc[j][3]);
        }
    }
}

// ---------------------------------------------------------------------------
// Kernel 2: per-batch FC via mma.sync tf32 with cp.async double buffering.
// K=512 in 8 chunks of 64; buffers A0@0 A1@4352 W0@8704 W1@13056 (69.6 KB).
// ---------------------------------------------------------------------------
static constexpr int SMEM3 = 17408 * 4;

__global__ __launch_bounds__(256) void fc_mma(
    const float* __restrict__ Wfc, float* __restrict__ out)
{
    extern __shared__ float sm[];
    const int b = blockIdx.x, tid = threadIdx.x;
    const int wid = tid >> 5, lane = tid & 31;
    const int lr = lane >> 2, lc = lane & 3;
    const float* A = g_o + (size_t)b * Nc * 512;
    const uint32_t sbase = smem_u32(sm);

    auto issue = [&](int kc, int sel) {
        #pragma unroll
        for (int j = 0; j < 4; j++) {
            const int i = tid + j * 256;            // 0..1023
            const int r = i >> 4, f4 = i & 15;
            cp16(sbase + (uint32_t)(sel * 4352 + r * 68 + f4 * 4) * 4,
                 A + r * 512 + kc * 64 + f4 * 4);
        }
        #pragma unroll
        for (int j = 0; j < 4; j++) {
            const int i = tid + j * 256;
            const int r = i >> 4, f4 = i & 15;
            cp16(sbase + (uint32_t)(8704 + sel * 4352 + r * 68 + f4 * 4) * 4,
                 Wfc + r * 512 + kc * 64 + f4 * 4);
        }
        CP_COMMIT();
    };

    issue(0, 0);
    issue(1, 1);

    const int m0 = (wid >> 1) * 16;
    const int n0 = (wid & 1) * 32;
    float acc[4][4] = {};

    for (int kc = 0; kc < 8; kc++) {
        if (kc < 7) { CP_WAIT(1); } else { CP_WAIT(0); }
        __syncthreads();
        const int sel = kc & 1;
        const float* s_A = sm + sel * 4352;
        const float* s_W = sm + 8704 + sel * 4352;
        #pragma unroll
        for (int k8 = 0; k8 < 8; k8++) {
            const int k0 = k8 * 8;
            uint32_t a[4];
            a[0] = __float_as_uint(tf32r(s_A[(m0 + lr)     * 68 + k0 + lc]));
            a[1] = __float_as_uint(tf32r(s_A[(m0 + lr + 8) * 68 + k0 + lc]));
            a[2] = __float_as_uint(tf32r(s_A[(m0 + lr)     * 68 + k0 + lc + 4]));
            a[3] = __float_as_uint(tf32r(s_A[(m0 + lr + 8) * 68 + k0 + lc + 4]));
            #pragma unroll
            for (int t = 0; t < 4; t++) {
                uint32_t bfr[2];
                bfr[0] = __float_as_uint(tf32r(s_W[(n0 + t * 8 + lr) * 68 + k0 + lc]));
                bfr[1] = __float_as_uint(tf32r(s_W[(n0 + t * 8 + lr) * 68 + k0 + lc + 4]));
                mma16n8k8(acc[t], a, bfr);
            }
        }
        __syncthreads();
        if (kc + 2 < 8) issue(kc + 2, sel);
    }

    float* ob = out + (size_t)b * 4096;
    #pragma unroll
    for (int t = 0; t < 4; t++) {
        const int o = n0 + t * 8 + lc * 2;
        *(float2*)(ob + (m0 + lr) * 64 + o)     = make_float2(acc[t][0], acc[t][1]);
        *(float2*)(ob + (m0 + lr + 8) * 64 + o) = make_float2(acc[t][2], acc[t][3]);
    }
}

// ---------------------------------------------------------------------------
extern "C" void kernel_launch(void* const* d_in, const int* in_sizes, int n_in,
                              void* d_out, int out_size) {
    const float* feat  = (const float*)d_in[0];
    const int*   sidx  = (const int*)  d_in[1];
    const float* gamma = (const float*)d_in[2];
    const float* beta  = (const float*)d_in[3];
    const float* Wq    = (const float*)d_in[4];
    const float* Wk    = (const float*)d_in[5];
    const float* Wv1   = (const float*)d_in[6];
    const float* Wv2   = (const float*)d_in[7];
    const float* Wfc   = (const float*)d_in[8];

    float* out  = (float*)d_out;
    float* attn = out + (size_t)Bc * Nc * 64;

    cudaFuncSetAttribute(ln_y_kernel, cudaFuncAttributeMaxDynamicSharedMemorySize, SMEMY);
    cudaFuncSetAttribute(head_mma,    cudaFuncAttributeMaxDynamicSharedMemorySize, SMEM2);
    cudaFuncSetAttribute(fc_mma,      cudaFuncAttributeMaxDynamicSharedMemorySize, SMEM3);

    ln_y_kernel<<<Bc, 256, SMEMY>>>(feat, gamma, beta);
    head_mma<<<dim3(Hc, Bc), 256, SMEM2>>>(feat, sidx, Wk, Wv1, Wv2, Wq, attn);
    fc_mma<<<Bc, 256, SMEM3>>>(Wfc, out);
}

// round 8
// speedup vs baseline: 3.8761x; 1.0467x over previous
#include <cuda_runtime.h>
#include <math.h>
#include <stdint.h>

#define Bc 512
#define Mc 4096
#define Nc 64
#define Hc 8

// Scratch (device globals, allocation-free rule)
__device__ float g_y[(size_t)Bc * Mc];              // 8 MB, LN'd features (tf32, affine)
__device__ float g_o[(size_t)Bc * Nc * 512];        // 64 MB, (b,n, h*64+p)

__device__ __forceinline__ float tf32r(float x) {
    float r; asm("cvt.rna.tf32.f32 %0, %1;" : "=f"(r) : "f"(x)); return r;
}
__device__ __forceinline__ void mma16n8k8(float* c, const uint32_t* a, const uint32_t* b) {
    asm volatile(
        "mma.sync.aligned.m16n8k8.row.col.f32.tf32.tf32.f32 "
        "{%0,%1,%2,%3}, {%4,%5,%6,%7}, {%8,%9}, {%0,%1,%2,%3};"
        : "+f"(c[0]), "+f"(c[1]), "+f"(c[2]), "+f"(c[3])
        : "r"(a[0]), "r"(a[1]), "r"(a[2]), "r"(a[3]), "r"(b[0]), "r"(b[1]));
}
__device__ __forceinline__ uint32_t smem_u32(const void* p) {
    uint32_t a;
    asm("{ .reg .u64 t; cvta.to.shared.u64 t, %1; cvt.u32.u64 %0, t; }" : "=r"(a) : "l"(p));
    return a;
}
__device__ __forceinline__ void cp16(uint32_t s, const void* g) {
    asm volatile("cp.async.cg.shared.global [%0], [%1], 16;" :: "r"(s), "l"(g));
}
#define CP_COMMIT()  asm volatile("cp.async.commit_group;" ::: "memory")
#define CP_WAIT(n)   asm volatile("cp.async.wait_group %0;" :: "n"(n) : "memory")

// ---------------------------------------------------------------------------
// Kernel 0: LayerNorm only -> g_y (tf32, gamma/beta applied). grid=B, 256 thr.
// ---------------------------------------------------------------------------
static constexpr int SMEMY = 4096 * 4 + 80;

__global__ __launch_bounds__(256) void ln_y_kernel(
    const float* __restrict__ feat, const float* __restrict__ gamma,
    const float* __restrict__ beta)
{
    extern __shared__ float sm[];
    float* s_x = sm;             // 4096
    float* s_red = sm + 4096;    // 18

    const int b = blockIdx.x, tid = threadIdx.x;
    const int wid = tid >> 5, lane = tid & 31;
    const float4* x4 = (const float4*)(feat + (size_t)b * Mc);

    float sum = 0.f, sq = 0.f;
    for (int i = tid; i < 1024; i += 256) {
        float4 v = x4[i];
        *(float4*)&s_x[i * 4] = v;
        sum += v.x + v.y + v.z + v.w;
        sq  += v.x*v.x + v.y*v.y + v.z*v.z + v.w*v.w;
    }
    #pragma unroll
    for (int o = 16; o; o >>= 1) {
        sum += __shfl_xor_sync(~0u, sum, o);
        sq  += __shfl_xor_sync(~0u, sq,  o);
    }
    if (lane == 0) { s_red[wid] = sum; s_red[wid + 8] = sq; }
    __syncthreads();
    if (tid == 0) {
        float S = 0.f, Q = 0.f;
        #pragma unroll
        for (int i = 0; i < 8; i++) { S += s_red[i]; Q += s_red[i + 8]; }
        float mu = S * (1.f / Mc);
        s_red[16] = mu;
        s_red[17] = rsqrtf(Q * (1.f / Mc) - mu * mu + 1e-5f);
    }
    __syncthreads();
    const float mu = s_red[16], rstd = s_red[17];
    float4* y4 = (float4*)(g_y + (size_t)b * Mc);
    const float4* g4 = (const float4*)gamma;
    const float4* b4 = (const float4*)beta;
    for (int i = tid; i < 1024; i += 256) {
        float4 v = *(float4*)&s_x[i * 4];
        float4 g = g4[i], bb = b4[i], y;
        y.x = tf32r((v.x - mu) * rstd * g.x + bb.x);
        y.y = tf32r((v.y - mu) * rstd * g.y + bb.y);
        y.z = tf32r((v.z - mu) * rstd * g.z + bb.z);
        y.w = tf32r((v.w - mu) * rstd * g.w + bb.w);
        y4[i] = y;
    }
}

// ---------------------------------------------------------------------------
// Kernel 1: per-(b,h) head; cp.async-staged, phase-overlapped, mma tf32.
// smem (floats):
//   @0     kf[64][68] (4352)   — gathered feats; S overlay in P3+
//   @4352  feat[4096] (4352)   — raw feats; vT overlay in phase B
//   @8704  y[64][68]  (4352)   — LN'd; dies after q GEMM; then keyT[64][36]@8704
//                                 + q[64][36]@11008
//   @13312 wk[32][68] (2176)
//   @15488 wq[32][68] (2176)
//   @17664 wv[16]
// total 17680 floats = 70.7 KB -> 3 CTA/SM.
// ---------------------------------------------------------------------------
static constexpr int SMEM2 = 17680 * 4;

__global__ __launch_bounds__(256) void head_mma(
    const float* __restrict__ feat, const int* __restrict__ sidx,
    const float* __restrict__ Wk, const float* __restrict__ Wv1,
    const float* __restrict__ Wv2, const float* __restrict__ Wq,
    float* __restrict__ attn_out)
{
    extern __shared__ float sm[];
    float* s_kf   = sm;            // [64][68]
    float* s_S    = sm;            // overlay
    float* s_vT   = sm + 4352;     // [p][n] pitch 68
    float* s_feat = sm + 4352;
    float* s_y    = sm + 8704;     // [n][k] pitch 68 (dies after q GEMM)
    float* s_keyT = sm + 8704;     // [n][d] pitch 36
    float* s_q    = sm + 11008;    // [q][d] pitch 36
    float* s_wk   = sm + 13312;    // [d][k] pitch 68
    float* s_wq   = sm + 15488;    // [e][k] pitch 68 (raw)
    float* s_wv   = sm + 17664;    // wv1[12], wv2[4]

    const int h = blockIdx.x, b = blockIdx.y, tid = threadIdx.x;
    const int wid = tid >> 5, lane = tid & 31;
    const int lr = lane >> 2, lc = lane & 3;
    const int* idx = sidx + (size_t)h * Mc;
    const uint32_t sbase = smem_u32(sm);

    // ---- issue async staging: G1 = {y, wq}, G2 = {feat, wk} ----
    {
        const float* yg = g_y + (size_t)b * Mc;
        #pragma unroll
        for (int j = 0; j < 4; j++) {
            int i = tid + j * 256;               // 0..1023
            int n = i >> 4, k4 = i & 15;
            cp16(sbase + (uint32_t)(8704 + n * 68 + k4 * 4) * 4, yg + i * 4);
        }
        #pragma unroll
        for (int j = 0; j < 2; j++) {
            int i = tid + j * 256;               // 0..511
            int e = i >> 4, k4 = i & 15;
            cp16(sbase + (uint32_t)(15488 + e * 68 + k4 * 4) * 4,
                 Wq + (size_t)(h * 32 + e) * 64 + k4 * 4);
        }
        CP_COMMIT();
        const float* xg = feat + (size_t)b * Mc;
        #pragma unroll
        for (int j = 0; j < 4; j++) {
            int i = tid + j * 256;
            cp16(sbase + (uint32_t)(4352 + i * 4) * 4, xg + i * 4);
        }
        #pragma unroll
        for (int j = 0; j < 2; j++) {
            int i = tid + j * 256;               // 0..511
            int d = i >> 4, k4 = i & 15;
            cp16(sbase + (uint32_t)(13312 + d * 68 + k4 * 4) * 4,
                 Wk + (size_t)h * 2048 + i * 4);
        }
        CP_COMMIT();
        if (tid < 12) s_wv[tid] = Wv1[h * 12 + tid];
        if (tid >= 32 && tid < 36) s_wv[12 + tid - 32] = Wv2[h * 4 + tid - 32];
    }

    // ---- phase A1: wait y/wq, q GEMM into registers (feat/wk still in flight)
    CP_WAIT(1);
    __syncthreads();

    float qacc[2][4] = {};
    const int qm = (wid & 3) * 16;
    const int qd = (wid >> 2) * 16;
    {
        #pragma unroll
        for (int k8 = 0; k8 < 8; k8++) {
            const int k0 = k8 * 8;
            uint32_t a[4];
            a[0] = __float_as_uint(s_y[(qm + lr)     * 68 + k0 + lc]);
            a[1] = __float_as_uint(s_y[(qm + lr + 8) * 68 + k0 + lc]);
            a[2] = __float_as_uint(s_y[(qm + lr)     * 68 + k0 + lc + 4]);
            a[3] = __float_as_uint(s_y[(qm + lr + 8) * 68 + k0 + lc + 4]);
            #pragma unroll
            for (int t = 0; t < 2; t++) {
                uint32_t bfr[2];
                bfr[0] = __float_as_uint(tf32r(s_wq[(qd + t * 8 + lr) * 68 + k0 + lc]));
                bfr[1] = __float_as_uint(tf32r(s_wq[(qd + t * 8 + lr) * 68 + k0 + lc + 4]));
                mma16n8k8(qacc[t], a, bfr);
            }
        }
    }

    // ---- phase A2: wait feat/wk, gather kf (kf region is free), conv pad ----
    CP_WAIT(0);
    __syncthreads();
    {
        const int4* idx4 = (const int4*)idx;
        #pragma unroll
        for (int j = 0; j < 4; j++) {
            int i = tid + j * 256;               // 0..1023
            int4 v = idx4[i];
            int n = i >> 4, k = (i & 15) * 4;
            float4 g = make_float4(s_feat[v.x], s_feat[v.y], s_feat[v.z], s_feat[v.w]);
            *(float4*)&s_kf[n * 68 + k] = g;
        }
        if (tid < 128) s_kf[(tid >> 1) * 68 + 64 + (tid & 1)] = 0.f;
    }
    __syncthreads();   // y reads done (A1) -> q/keyT writes now safe

    // ---- phase B: q frag store (x 1/64), key GEMM, conv ----
    {
        #pragma unroll
        for (int t = 0; t < 2; t++) {
            const int d = qd + t * 8 + lc * 2;
            s_q[(qm + lr) * 36 + d]         = tf32r(qacc[t][0] * 0.015625f);
            s_q[(qm + lr) * 36 + d + 1]     = tf32r(qacc[t][1] * 0.015625f);
            s_q[(qm + lr + 8) * 36 + d]     = tf32r(qacc[t][2] * 0.015625f);
            s_q[(qm + lr + 8) * 36 + d + 1] = tf32r(qacc[t][3] * 0.015625f);
        }
    }
    {
        const int m0 = (wid & 1) * 16;        // d tile
        const int nb = (wid >> 1) * 8;        // n tiles {nb, nb+32}
        float acc[2][4] = {};
        #pragma unroll
        for (int k8 = 0; k8 < 8; k8++) {
            const int k0 = k8 * 8;
            uint32_t a[4];
            a[0] = __float_as_uint(tf32r(s_wk[(m0 + lr)     * 68 + k0 + lc]));
            a[1] = __float_as_uint(tf32r(s_wk[(m0 + lr + 8) * 68 + k0 + lc]));
            a[2] = __float_as_uint(tf32r(s_wk[(m0 + lr)     * 68 + k0 + lc + 4]));
            a[3] = __float_as_uint(tf32r(s_wk[(m0 + lr + 8) * 68 + k0 + lc + 4]));
            #pragma unroll
            for (int t = 0; t < 2; t++) {
                const int nn = nb + t * 32;
                uint32_t bfr[2];
                bfr[0] = __float_as_uint(tf32r(s_kf[(nn + lr) * 68 + k0 + lc]));
                bfr[1] = __float_as_uint(tf32r(s_kf[(nn + lr) * 68 + k0 + lc + 4]));
                mma16n8k8(acc[t], a, bfr);
            }
        }
        #pragma unroll
        for (int t = 0; t < 2; t++) {
            const int n = nb + t * 32 + lc * 2, d = m0 + lr;
            s_keyT[n * 36 + d]           = tf32r(acc[t][0]);
            s_keyT[(n + 1) * 36 + d]     = tf32r(acc[t][1]);
            s_keyT[n * 36 + d + 8]       = tf32r(acc[t][2]);
            s_keyT[(n + 1) * 36 + d + 8] = tf32r(acc[t][3]);
        }
    }
    {
        const int n = tid >> 2, p0 = (tid & 3) * 16;
        const float* kr = s_kf + n * 68;
        float w0[4], w1[4], w2[4], w3[4];
        #pragma unroll
        for (int d = 0; d < 4; d++) {
            w0[d] = s_wv[d * 3]; w1[d] = s_wv[d * 3 + 1];
            w2[d] = s_wv[d * 3 + 2]; w3[d] = s_wv[12 + d];
        }
        float x0 = kr[p0], x1 = kr[p0 + 1];
        #pragma unroll
        for (int i = 0; i < 16; i++) {
            float x2 = kr[p0 + i + 2];
            float acc = x0;
            #pragma unroll
            for (int d = 0; d < 4; d++)
                acc += fmaxf(x0 * w0[d] + x1 * w1[d] + x2 * w2[d], 0.f) * w3[d];
            s_vT[(p0 + i) * 68 + n] = tf32r(acc);
            x0 = x1; x1 = x2;
        }
    }
    __syncthreads();

    const int m0 = (wid >> 1) * 16;       // q tile
    const int nb4 = (wid & 1) * 4;        // 4 n-tiles

    // ---- P3: S[q][n] = sum_d q[q][d] * keyT[n][d]  (kf dead -> S overlay) ----
    {
        float acc[4][4] = {};
        #pragma unroll
        for (int k8 = 0; k8 < 4; k8++) {
            const int k0 = k8 * 8;
            uint32_t a[4];
            a[0] = __float_as_uint(s_q[(m0 + lr)     * 36 + k0 + lc]);
            a[1] = __float_as_uint(s_q[(m0 + lr + 8) * 36 + k0 + lc]);
            a[2] = __float_as_uint(s_q[(m0 + lr)     * 36 + k0 + lc + 4]);
            a[3] = __float_as_uint(s_q[(m0 + lr + 8) * 36 + k0 + lc + 4]);
            #pragma unroll
            for (int j = 0; j < 4; j++) {
                const int nn = (nb4 + j) * 8;
                uint32_t bfr[2];
                bfr[0] = __float_as_uint(s_keyT[(nn + lr) * 36 + k0 + lc]);
                bfr[1] = __float_as_uint(s_keyT[(nn + lr) * 36 + k0 + lc + 4]);
                mma16n8k8(acc[j], a, bfr);
            }
        }
        #pragma unroll
        for (int j = 0; j < 4; j++) {
            const int col = (nb4 + j) * 8 + lc * 2;
            *(float2*)&s_S[(m0 + lr)     * 68 + col] = make_float2(acc[j][0], acc[j][1]);
            *(float2*)&s_S[(m0 + lr + 8) * 68 + col] = make_float2(acc[j][2], acc[j][3]);
        }
    }
    __syncthreads();

    // ---- P4: softmax rows of S; global attn fp32, smem tf32 ----
    {
        const int r = tid >> 2, s3 = tid & 3;
        float* row = s_S + r * 68 + s3 * 16;
        float4 v0 = *(float4*)&row[0], v1 = *(float4*)&row[4];
        float4 v2 = *(float4*)&row[8], v3 = *(float4*)&row[12];
        float mx = fmaxf(fmaxf(fmaxf(v0.x, v0.y), fmaxf(v0.z, v0.w)),
                         fmaxf(fmaxf(v1.x, v1.y), fmaxf(v1.z, v1.w)));
        mx = fmaxf(mx, fmaxf(fmaxf(fmaxf(v2.x, v2.y), fmaxf(v2.z, v2.w)),
                             fmaxf(fmaxf(v3.x, v3.y), fmaxf(v3.z, v3.w))));
        mx = fmaxf(mx, __shfl_xor_sync(~0u, mx, 1));
        mx = fmaxf(mx, __shfl_xor_sync(~0u, mx, 2));
        float e[16];
        e[0]=__expf(v0.x-mx); e[1]=__expf(v0.y-mx); e[2]=__expf(v0.z-mx); e[3]=__expf(v0.w-mx);
        e[4]=__expf(v1.x-mx); e[5]=__expf(v1.y-mx); e[6]=__expf(v1.z-mx); e[7]=__expf(v1.w-mx);
        e[8]=__expf(v2.x-mx); e[9]=__expf(v2.y-mx); e[10]=__expf(v2.z-mx); e[11]=__expf(v2.w-mx);
        e[12]=__expf(v3.x-mx); e[13]=__expf(v3.y-mx); e[14]=__expf(v3.z-mx); e[15]=__expf(v3.w-mx);
        float ssum = 0.f;
        #pragma unroll
        for (int i = 0; i < 16; i++) ssum += e[i];
        ssum += __shfl_xor_sync(~0u, ssum, 1);
        ssum += __shfl_xor_sync(~0u, ssum, 2);
        const float inv = 1.f / ssum;
        float* gattn = attn_out + (((size_t)(b * Hc + h) * Nc + r) * Nc) + s3 * 16;
        #pragma unroll
        for (int u = 0; u < 4; u++) {
            float p0 = e[4*u] * inv, p1 = e[4*u+1] * inv,
                  p2 = e[4*u+2] * inv, p3 = e[4*u+3] * inv;
            *(float4*)&gattn[4 * u] = make_float4(p0, p1, p2, p3);
            *(float4*)&row[4 * u]   = make_float4(tf32r(p0), tf32r(p1), tf32r(p2), tf32r(p3));
        }
    }
    __syncthreads();

    // ---- P5: out[q][p] = sum_n attn[q][n] * vT[p][n] -> g_o ----
    {
        float acc[4][4] = {};
        #pragma unroll
        for (int k8 = 0; k8 < 8; k8++) {
            const int k0 = k8 * 8;
            uint32_t a[4];
            a[0] = __float_as_uint(s_S[(m0 + lr)     * 68 + k0 + lc]);
            a[1] = __float_as_uint(s_S[(m0 + lr + 8) * 68 + k0 + lc]);
            a[2] = __float_as_uint(s_S[(m0 + lr)     * 68 + k0 + lc + 4]);
            a[3] = __float_as_uint(s_S[(m0 + lr + 8) * 68 + k0 + lc + 4]);
            #pragma unroll
            for (int j = 0; j < 4; j++) {
                const int pp = (nb4 + j) * 8;
                uint32_t bfr[2];
                bfr[0] = __float_as_uint(s_vT[(pp + lr) * 68 + k0 + lc]);
                bfr[1] = __float_as_uint(s_vT[(pp + lr) * 68 + k0 + lc + 4]);
                mma16n8k8(acc[j], a, bfr);
            }
        }
        float* ob = g_o + ((size_t)b * Nc) * 512 + h * 64;
        #pragma unroll
        for (int j = 0; j < 4; j++) {
            const int p = (nb4 + j) * 8 + lc * 2;
            *(float2*)(ob + (size_t)(m0 + lr) * 512 + p)     = make_float2(acc[j][0], acc[j][1]);
            *(float2*)(ob + (size_t)(m0 + lr + 8) * 512 + p) = make_float2(acc[j][2], acc[j][3]);
        }
    }
}

// ---------------------------------------------------------------------------
// Kernel 2: per-batch FC via mma.sync tf32 with cp.async double buffering.
// ---------------------------------------------------------------------------
static constexpr int SMEM3 = 17408 * 4;

__global__ __launch_bounds__(256) void fc_mma(
    const float* __restrict__ Wfc, float* __restrict__ out)
{
    extern __shared__ float sm[];
    const int b = blockIdx.x, tid = threadIdx.x;
    const int wid = tid >> 5, lane = tid & 31;
    const int lr = lane >> 2, lc = lane & 3;
    const float* A = g_o + (size_t)b * Nc * 512;
    const uint32_t sbase = smem_u32(sm);

    auto issue = [&](int kc, int sel) {
        #pragma unroll
        for (int j = 0; j < 4; j++) {
            const int i = tid + j * 256;
            const int r = i >> 4, f4 = i & 15;
            cp16(sbase + (uint32_t)(sel * 4352 + r * 68 + f4 * 4) * 4,
                 A + r * 512 + kc * 64 + f4 * 4);
        }
        #pragma unroll
        for (int j = 0; j < 4; j++) {
            const int i = tid + j * 256;
            const int r = i >> 4, f4 = i & 15;
            cp16(sbase + (uint32_t)(8704 + sel * 4352 + r * 68 + f4 * 4) * 4,
                 Wfc + r * 512 + kc * 64 + f4 * 4);
        }
        CP_COMMIT();
    };

    issue(0, 0);
    issue(1, 1);

    const int m0 = (wid >> 1) * 16;
    const int n0 = (wid & 1) * 32;
    float acc[4][4] = {};

    for (int kc = 0; kc < 8; kc++) {
        if (kc < 7) { CP_WAIT(1); } else { CP_WAIT(0); }
        __syncthreads();
        const int sel = kc & 1;
        const float* s_A = sm + sel * 4352;
        const float* s_W = sm + 8704 + sel * 4352;
        #pragma unroll
        for (int k8 = 0; k8 < 8; k8++) {
            const int k0 = k8 * 8;
            uint32_t a[4];
            a[0] = __float_as_uint(tf32r(s_A[(m0 + lr)     * 68 + k0 + lc]));
            a[1] = __float_as_uint(tf32r(s_A[(m0 + lr + 8) * 68 + k0 + lc]));
            a[2] = __float_as_uint(tf32r(s_A[(m0 + lr)     * 68 + k0 + lc + 4]));
            a[3] = __float_as_uint(tf32r(s_A[(m0 + lr + 8) * 68 + k0 + lc + 4]));
            #pragma unroll
            for (int t = 0; t < 4; t++) {
                uint32_t bfr[2];
                bfr[0] = __float_as_uint(tf32r(s_W[(n0 + t * 8 + lr) * 68 + k0 + lc]));
                bfr[1] = __float_as_uint(tf32r(s_W[(n0 + t * 8 + lr) * 68 + k0 + lc + 4]));
                mma16n8k8(acc[t], a, bfr);
            }
        }
        __syncthreads();
        if (kc + 2 < 8) issue(kc + 2, sel);
    }

    float* ob = out + (size_t)b * 4096;
    #pragma unroll
    for (int t = 0; t < 4; t++) {
        const int o = n0 + t * 8 + lc * 2;
        *(float2*)(ob + (m0 + lr) * 64 + o)     = make_float2(acc[t][0], acc[t][1]);
        *(float2*)(ob + (m0 + lr + 8) * 64 + o) = make_float2(acc[t][2], acc[t][3]);
    }
}

// ---------------------------------------------------------------------------
extern "C" void kernel_launch(void* const* d_in, const int* in_sizes, int n_in,
                              void* d_out, int out_size) {
    const float* feat  = (const float*)d_in[0];
    const int*   sidx  = (const int*)  d_in[1];
    const float* gamma = (const float*)d_in[2];
    const float* beta  = (const float*)d_in[3];
    const float* Wq    = (const float*)d_in[4];
    const float* Wk    = (const float*)d_in[5];
    const float* Wv1   = (const float*)d_in[6];
    const float* Wv2   = (const float*)d_in[7];
    const float* Wfc   = (const float*)d_in[8];

    float* out  = (float*)d_out;
    float* attn = out + (size_t)Bc * Nc * 64;

    cudaFuncSetAttribute(ln_y_kernel, cudaFuncAttributeMaxDynamicSharedMemorySize, SMEMY);
    cudaFuncSetAttribute(head_mma,    cudaFuncAttributeMaxDynamicSharedMemorySize, SMEM2);
    cudaFuncSetAttribute(fc_mma,      cudaFuncAttributeMaxDynamicSharedMemorySize, SMEM3);

    ln_y_kernel<<<Bc, 256, SMEMY>>>(feat, gamma, beta);
    head_mma<<<dim3(Hc, Bc), 256, SMEM2>>>(feat, sidx, Wk, Wv1, Wv2, Wq, attn);
    fc_mma<<<Bc, 256, SMEM3>>>(Wfc, out);
}

// round 9
// speedup vs baseline: 3.9168x; 1.0105x over previous
#include <cuda_runtime.h>
#include <math.h>
#include <stdint.h>

#define Bc 512
#define Mc 4096
#define Nc 64
#define Hc 8

// Scratch (device globals, allocation-free rule)
__device__ float g_y[(size_t)Bc * Mc];              // 8 MB, LN'd features (tf32, affine)

__device__ __forceinline__ float tf32r(float x) {
    float r; asm("cvt.rna.tf32.f32 %0, %1;" : "=f"(r) : "f"(x)); return r;
}
__device__ __forceinline__ void mma16n8k8(float* c, const uint32_t* a, const uint32_t* b) {
    asm volatile(
        "mma.sync.aligned.m16n8k8.row.col.f32.tf32.tf32.f32 "
        "{%0,%1,%2,%3}, {%4,%5,%6,%7}, {%8,%9}, {%0,%1,%2,%3};"
        : "+f"(c[0]), "+f"(c[1]), "+f"(c[2]), "+f"(c[3])
        : "r"(a[0]), "r"(a[1]), "r"(a[2]), "r"(a[3]), "r"(b[0]), "r"(b[1]));
}
__device__ __forceinline__ uint32_t smem_u32(const void* p) {
    uint32_t a;
    asm("{ .reg .u64 t; cvta.to.shared.u64 t, %1; cvt.u32.u64 %0, t; }" : "=r"(a) : "l"(p));
    return a;
}
__device__ __forceinline__ void cp16(uint32_t s, const void* g) {
    asm volatile("cp.async.cg.shared.global [%0], [%1], 16;" :: "r"(s), "l"(g));
}
__device__ __forceinline__ void redg_add(float* g, float v) {
    asm volatile("red.global.add.f32 [%0], %1;" :: "l"(g), "f"(v) : "memory");
}
#define CP_COMMIT()  asm volatile("cp.async.commit_group;" ::: "memory")
#define CP_WAIT(n)   asm volatile("cp.async.wait_group %0;" :: "n"(n) : "memory")

// ---------------------------------------------------------------------------
// Kernel Z: zero the `out` region of d_out (poisoned 0xAA by harness).
// ---------------------------------------------------------------------------
__global__ __launch_bounds__(256) void zero_out(float* __restrict__ out)
{
    float4* o4 = (float4*)out;                   // 2M floats = 512K float4
    const int base = blockIdx.x * 1024 + threadIdx.x;
    #pragma unroll
    for (int j = 0; j < 4; j++)
        o4[base + j * 256] = make_float4(0.f, 0.f, 0.f, 0.f);
}

// ---------------------------------------------------------------------------
// Kernel 0: LayerNorm only -> g_y (tf32, gamma/beta applied). grid=B, 256 thr.
// ---------------------------------------------------------------------------
static constexpr int SMEMY = 4096 * 4 + 80;

__global__ __launch_bounds__(256) void ln_y_kernel(
    const float* __restrict__ feat, const float* __restrict__ gamma,
    const float* __restrict__ beta)
{
    extern __shared__ float sm[];
    float* s_x = sm;             // 4096
    float* s_red = sm + 4096;    // 18

    const int b = blockIdx.x, tid = threadIdx.x;
    const int wid = tid >> 5, lane = tid & 31;
    const float4* x4 = (const float4*)(feat + (size_t)b * Mc);

    float sum = 0.f, sq = 0.f;
    for (int i = tid; i < 1024; i += 256) {
        float4 v = x4[i];
        *(float4*)&s_x[i * 4] = v;
        sum += v.x + v.y + v.z + v.w;
        sq  += v.x*v.x + v.y*v.y + v.z*v.z + v.w*v.w;
    }
    #pragma unroll
    for (int o = 16; o; o >>= 1) {
        sum += __shfl_xor_sync(~0u, sum, o);
        sq  += __shfl_xor_sync(~0u, sq,  o);
    }
    if (lane == 0) { s_red[wid] = sum; s_red[wid + 8] = sq; }
    __syncthreads();
    if (tid == 0) {
        float S = 0.f, Q = 0.f;
        #pragma unroll
        for (int i = 0; i < 8; i++) { S += s_red[i]; Q += s_red[i + 8]; }
        float mu = S * (1.f / Mc);
        s_red[16] = mu;
        s_red[17] = rsqrtf(Q * (1.f / Mc) - mu * mu + 1e-5f);
    }
    __syncthreads();
    const float mu = s_red[16], rstd = s_red[17];
    float4* y4 = (float4*)(g_y + (size_t)b * Mc);
    const float4* g4 = (const float4*)gamma;
    const float4* b4 = (const float4*)beta;
    for (int i = tid; i < 1024; i += 256) {
        float4 v = *(float4*)&s_x[i * 4];
        float4 g = g4[i], bb = b4[i], y;
        y.x = tf32r((v.x - mu) * rstd * g.x + bb.x);
        y.y = tf32r((v.y - mu) * rstd * g.y + bb.y);
        y.z = tf32r((v.z - mu) * rstd * g.z + bb.z);
        y.w = tf32r((v.w - mu) * rstd * g.w + bb.w);
        y4[i] = y;
    }
}

// ---------------------------------------------------------------------------
// Kernel 1: per-(b,h) head with fused FC partial (REDG accumulate to out).
// smem (floats):
//   @0     kf[64][68] — gathered feats; S overlay (P3+); hout overlay (P6)
//   @4352  feat[4096] — raw feats; vT overlay in phase B
//   @8704  y[64][68]  — dies after q GEMM; then keyT@8704 + q@11008;
//                        after P3: wfc[64][68]@8704
//   @13312 wk[32][68]
//   @15488 wq[32][68]
//   @17664 wv[16]
// total 17680 floats = 70.7 KB -> 3 CTA/SM.
// ---------------------------------------------------------------------------
static constexpr int SMEM2 = 17680 * 4;

__global__ __launch_bounds__(256) void head_mma(
    const float* __restrict__ feat, const int* __restrict__ sidx,
    const float* __restrict__ Wk, const float* __restrict__ Wv1,
    const float* __restrict__ Wv2, const float* __restrict__ Wq,
    const float* __restrict__ Wfc,
    float* __restrict__ out, float* __restrict__ attn_out)
{
    extern __shared__ float sm[];
    float* s_kf   = sm;            // [64][68]
    float* s_S    = sm;            // overlay
    float* s_vT   = sm + 4352;     // [p][n] pitch 68
    float* s_feat = sm + 4352;
    float* s_y    = sm + 8704;     // dies after q GEMM
    float* s_keyT = sm + 8704;     // [n][d] pitch 36
    float* s_q    = sm + 11008;    // [q][d] pitch 36
    float* s_wfc  = sm + 8704;     // [o][p] pitch 68 (after P3)
    float* s_wk   = sm + 13312;    // [d][k] pitch 68
    float* s_wq   = sm + 15488;    // [e][k] pitch 68 (raw)
    float* s_wv   = sm + 17664;    // wv1[12], wv2[4]

    const int h = blockIdx.x, b = blockIdx.y, tid = threadIdx.x;
    const int wid = tid >> 5, lane = tid & 31;
    const int lr = lane >> 2, lc = lane & 3;
    const int* idx = sidx + (size_t)h * Mc;
    const uint32_t sbase = smem_u32(sm);

    // ---- issue async staging: G1 = {y, wq}, G2 = {feat, wk} ----
    {
        const float* yg = g_y + (size_t)b * Mc;
        #pragma unroll
        for (int j = 0; j < 4; j++) {
            int i = tid + j * 256;               // 0..1023
            int n = i >> 4, k4 = i & 15;
            cp16(sbase + (uint32_t)(8704 + n * 68 + k4 * 4) * 4, yg + i * 4);
        }
        #pragma unroll
        for (int j = 0; j < 2; j++) {
            int i = tid + j * 256;               // 0..511
            int e = i >> 4, k4 = i & 15;
            cp16(sbase + (uint32_t)(15488 + e * 68 + k4 * 4) * 4,
                 Wq + (size_t)(h * 32 + e) * 64 + k4 * 4);
        }
        CP_COMMIT();
        const float* xg = feat + (size_t)b * Mc;
        #pragma unroll
        for (int j = 0; j < 4; j++) {
            int i = tid + j * 256;
            cp16(sbase + (uint32_t)(4352 + i * 4) * 4, xg + i * 4);
        }
        #pragma unroll
        for (int j = 0; j < 2; j++) {
            int i = tid + j * 256;               // 0..511
            int d = i >> 4, k4 = i & 15;
            cp16(sbase + (uint32_t)(13312 + d * 68 + k4 * 4) * 4,
                 Wk + (size_t)h * 2048 + i * 4);
        }
        CP_COMMIT();
        if (tid < 12) s_wv[tid] = Wv1[h * 12 + tid];
        if (tid >= 32 && tid < 36) s_wv[12 + tid - 32] = Wv2[h * 4 + tid - 32];
    }

    // ---- phase A1: wait y/wq, q GEMM into registers (feat/wk in flight) ----
    CP_WAIT(1);
    __syncthreads();

    float qacc[2][4] = {};
    const int qm = (wid & 3) * 16;
    const int qd = (wid >> 2) * 16;
    {
        #pragma unroll
        for (int k8 = 0; k8 < 8; k8++) {
            const int k0 = k8 * 8;
            uint32_t a[4];
            a[0] = __float_as_uint(s_y[(qm + lr)     * 68 + k0 + lc]);
            a[1] = __float_as_uint(s_y[(qm + lr + 8) * 68 + k0 + lc]);
            a[2] = __float_as_uint(s_y[(qm + lr)     * 68 + k0 + lc + 4]);
            a[3] = __float_as_uint(s_y[(qm + lr + 8) * 68 + k0 + lc + 4]);
            #pragma unroll
            for (int t = 0; t < 2; t++) {
                uint32_t bfr[2];
                bfr[0] = __float_as_uint(tf32r(s_wq[(qd + t * 8 + lr) * 68 + k0 + lc]));
                bfr[1] = __float_as_uint(tf32r(s_wq[(qd + t * 8 + lr) * 68 + k0 + lc + 4]));
                mma16n8k8(qacc[t], a, bfr);
            }
        }
    }

    // ---- phase A2: wait feat/wk, gather kf, conv pad ----
    CP_WAIT(0);
    __syncthreads();
    {
        const int4* idx4 = (const int4*)idx;
        #pragma unroll
        for (int j = 0; j < 4; j++) {
            int i = tid + j * 256;               // 0..1023
            int4 v = idx4[i];
            int n = i >> 4, k = (i & 15) * 4;
            float4 g = make_float4(s_feat[v.x], s_feat[v.y], s_feat[v.z], s_feat[v.w]);
            *(float4*)&s_kf[n * 68 + k] = g;
        }
        if (tid < 128) s_kf[(tid >> 1) * 68 + 64 + (tid & 1)] = 0.f;
    }
    __syncthreads();   // y reads done (A1) -> q/keyT writes now safe

    // ---- phase B: q frag store (x 1/64), key GEMM, conv ----
    {
        #pragma unroll
        for (int t = 0; t < 2; t++) {
            const int d = qd + t * 8 + lc * 2;
            s_q[(qm + lr) * 36 + d]         = tf32r(qacc[t][0] * 0.015625f);
            s_q[(qm + lr) * 36 + d + 1]     = tf32r(qacc[t][1] * 0.015625f);
            s_q[(qm + lr + 8) * 36 + d]     = tf32r(qacc[t][2] * 0.015625f);
            s_q[(qm + lr + 8) * 36 + d + 1] = tf32r(qacc[t][3] * 0.015625f);
        }
    }
    {
        const int m0 = (wid & 1) * 16;        // d tile
        const int nb = (wid >> 1) * 8;        // n tiles {nb, nb+32}
        float acc[2][4] = {};
        #pragma unroll
        for (int k8 = 0; k8 < 8; k8++) {
            const int k0 = k8 * 8;
            uint32_t a[4];
            a[0] = __float_as_uint(tf32r(s_wk[(m0 + lr)     * 68 + k0 + lc]));
            a[1] = __float_as_uint(tf32r(s_wk[(m0 + lr + 8) * 68 + k0 + lc]));
            a[2] = __float_as_uint(tf32r(s_wk[(m0 + lr)     * 68 + k0 + lc + 4]));
            a[3] = __float_as_uint(tf32r(s_wk[(m0 + lr + 8) * 68 + k0 + lc + 4]));
            #pragma unroll
            for (int t = 0; t < 2; t++) {
                const int nn = nb + t * 32;
                uint32_t bfr[2];
                bfr[0] = __float_as_uint(tf32r(s_kf[(nn + lr) * 68 + k0 + lc]));
                bfr[1] = __float_as_uint(tf32r(s_kf[(nn + lr) * 68 + k0 + lc + 4]));
                mma16n8k8(acc[t], a, bfr);
            }
        }
        #pragma unroll
        for (int t = 0; t < 2; t++) {
            const int n = nb + t * 32 + lc * 2, d = m0 + lr;
            s_keyT[n * 36 + d]           = tf32r(acc[t][0]);
            s_keyT[(n + 1) * 36 + d]     = tf32r(acc[t][1]);
            s_keyT[n * 36 + d + 8]       = tf32r(acc[t][2]);
            s_keyT[(n + 1) * 36 + d + 8] = tf32r(acc[t][3]);
        }
    }
    {
        const int n = tid >> 2, p0 = (tid & 3) * 16;
        const float* kr = s_kf + n * 68;
        float w0[4], w1[4], w2[4], w3[4];
        #pragma unroll
        for (int d = 0; d < 4; d++) {
            w0[d] = s_wv[d * 3]; w1[d] = s_wv[d * 3 + 1];
            w2[d] = s_wv[d * 3 + 2]; w3[d] = s_wv[12 + d];
        }
        float x0 = kr[p0], x1 = kr[p0 + 1];
        #pragma unroll
        for (int i = 0; i < 16; i++) {
            float x2 = kr[p0 + i + 2];
            float acc = x0;
            #pragma unroll
            for (int d = 0; d < 4; d++)
                acc += fmaxf(x0 * w0[d] + x1 * w1[d] + x2 * w2[d], 0.f) * w3[d];
            s_vT[(p0 + i) * 68 + n] = tf32r(acc);
            x0 = x1; x1 = x2;
        }
    }
    __syncthreads();

    const int m0 = (wid >> 1) * 16;       // q tile
    const int nb4 = (wid & 1) * 4;        // 4 n-tiles

    // ---- P3: S[q][n] = sum_d q[q][d] * keyT[n][d] -> S overlay ----
    {
        float acc[4][4] = {};
        #pragma unroll
        for (int k8 = 0; k8 < 4; k8++) {
            const int k0 = k8 * 8;
            uint32_t a[4];
            a[0] = __float_as_uint(s_q[(m0 + lr)     * 36 + k0 + lc]);
            a[1] = __float_as_uint(s_q[(m0 + lr + 8) * 36 + k0 + lc]);
            a[2] = __float_as_uint(s_q[(m0 + lr)     * 36 + k0 + lc + 4]);
            a[3] = __float_as_uint(s_q[(m0 + lr + 8) * 36 + k0 + lc + 4]);
            #pragma unroll
            for (int j = 0; j < 4; j++) {
                const int nn = (nb4 + j) * 8;
                uint32_t bfr[2];
                bfr[0] = __float_as_uint(s_keyT[(nn + lr) * 36 + k0 + lc]);
                bfr[1] = __float_as_uint(s_keyT[(nn + lr) * 36 + k0 + lc + 4]);
                mma16n8k8(acc[j], a, bfr);
            }
        }
        #pragma unroll
        for (int j = 0; j < 4; j++) {
            const int col = (nb4 + j) * 8 + lc * 2;
            *(float2*)&s_S[(m0 + lr)     * 68 + col] = make_float2(acc[j][0], acc[j][1]);
            *(float2*)&s_S[(m0 + lr + 8) * 68 + col] = make_float2(acc[j][2], acc[j][3]);
        }
    }
    __syncthreads();   // P3 done: keyT/q dead

    // ---- stage Wfc slice [o][p] = Wfc[o][h*64+p] into dead keyT/q region ----
    {
        #pragma unroll
        for (int j = 0; j < 4; j++) {
            int i = tid + j * 256;               // 0..1023
            int o = i >> 4, p4 = i & 15;
            cp16(sbase + (uint32_t)(8704 + o * 68 + p4 * 4) * 4,
                 Wfc + (size_t)o * 512 + h * 64 + p4 * 4);
        }
        CP_COMMIT();
    }

    // ---- P4: softmax rows of S; global attn fp32, smem tf32 ----
    {
        const int r = tid >> 2, s3 = tid & 3;
        float* row = s_S + r * 68 + s3 * 16;
        float4 v0 = *(float4*)&row[0], v1 = *(float4*)&row[4];
        float4 v2 = *(float4*)&row[8], v3 = *(float4*)&row[12];
        float mx = fmaxf(fmaxf(fmaxf(v0.x, v0.y), fmaxf(v0.z, v0.w)),
                         fmaxf(fmaxf(v1.x, v1.y), fmaxf(v1.z, v1.w)));
        mx = fmaxf(mx, fmaxf(fmaxf(fmaxf(v2.x, v2.y), fmaxf(v2.z, v2.w)),
                             fmaxf(fmaxf(v3.x, v3.y), fmaxf(v3.z, v3.w))));
        mx = fmaxf(mx, __shfl_xor_sync(~0u, mx, 1));
        mx = fmaxf(mx, __shfl_xor_sync(~0u, mx, 2));
        float e[16];
        e[0]=__expf(v0.x-mx); e[1]=__expf(v0.y-mx); e[2]=__expf(v0.z-mx); e[3]=__expf(v0.w-mx);
        e[4]=__expf(v1.x-mx); e[5]=__expf(v1.y-mx); e[6]=__expf(v1.z-mx); e[7]=__expf(v1.w-mx);
        e[8]=__expf(v2.x-mx); e[9]=__expf(v2.y-mx); e[10]=__expf(v2.z-mx); e[11]=__expf(v2.w-mx);
        e[12]=__expf(v3.x-mx); e[13]=__expf(v3.y-mx); e[14]=__expf(v3.z-mx); e[15]=__expf(v3.w-mx);
        float ssum = 0.f;
        #pragma unroll
        for (int i = 0; i < 16; i++) ssum += e[i];
        ssum += __shfl_xor_sync(~0u, ssum, 1);
        ssum += __shfl_xor_sync(~0u, ssum, 2);
        const float inv = 1.f / ssum;
        float* gattn = attn_out + (((size_t)(b * Hc + h) * Nc + r) * Nc) + s3 * 16;
        #pragma unroll
        for (int u = 0; u < 4; u++) {
            float p0 = e[4*u] * inv, p1 = e[4*u+1] * inv,
                  p2 = e[4*u+2] * inv, p3 = e[4*u+3] * inv;
            *(float4*)&gattn[4 * u] = make_float4(p0, p1, p2, p3);
            *(float4*)&row[4 * u]   = make_float4(tf32r(p0), tf32r(p1), tf32r(p2), tf32r(p3));
        }
    }
    __syncthreads();

    // ---- P5: hout[q][p] = sum_n attn[q][n] * vT[p][n] (registers) ----
    float hacc[4][4] = {};
    {
        #pragma unroll
        for (int k8 = 0; k8 < 8; k8++) {
            const int k0 = k8 * 8;
            uint32_t a[4];
            a[0] = __float_as_uint(s_S[(m0 + lr)     * 68 + k0 + lc]);
            a[1] = __float_as_uint(s_S[(m0 + lr + 8) * 68 + k0 + lc]);
            a[2] = __float_as_uint(s_S[(m0 + lr)     * 68 + k0 + lc + 4]);
            a[3] = __float_as_uint(s_S[(m0 + lr + 8) * 68 + k0 + lc + 4]);
            #pragma unroll
            for (int j = 0; j < 4; j++) {
                const int pp = (nb4 + j) * 8;
                uint32_t bfr[2];
                bfr[0] = __float_as_uint(s_vT[(pp + lr) * 68 + k0 + lc]);
                bfr[1] = __float_as_uint(s_vT[(pp + lr) * 68 + k0 + lc + 4]);
                mma16n8k8(hacc[j], a, bfr);
            }
        }
    }
    CP_WAIT(0);        // wfc landed
    __syncthreads();   // all P5 reads of S done -> hout overlay safe

    // ---- store hout (tf32) into S region ----
    {
        #pragma unroll
        for (int j = 0; j < 4; j++) {
            const int p = (nb4 + j) * 8 + lc * 2;
            *(float2*)&s_S[(m0 + lr) * 68 + p] =
                make_float2(tf32r(hacc[j][0]), tf32r(hacc[j][1]));
            *(float2*)&s_S[(m0 + lr + 8) * 68 + p] =
                make_float2(tf32r(hacc[j][2]), tf32r(hacc[j][3]));
        }
    }
    __syncthreads();

    // ---- P6: FC partial  po[n][o] = sum_p hout[n][p] * wfc[o][p]; REDG ----
    {
        const int fm = (wid >> 1) * 16;      // n rows
        const int fo = (wid & 1) * 32;       // o cols (4 n8-tiles)
        float acc[4][4] = {};
        #pragma unroll
        for (int k8 = 0; k8 < 8; k8++) {
            const int k0 = k8 * 8;
            uint32_t a[4];
            a[0] = __float_as_uint(s_S[(fm + lr)     * 68 + k0 + lc]);
            a[1] = __float_as_uint(s_S[(fm + lr + 8) * 68 + k0 + lc]);
            a[2] = __float_as_uint(s_S[(fm + lr)     * 68 + k0 + lc + 4]);
            a[3] = __float_as_uint(s_S[(fm + lr + 8) * 68 + k0 + lc + 4]);
            #pragma unroll
            for (int t = 0; t < 4; t++) {
                uint32_t bfr[2];
                bfr[0] = __float_as_uint(tf32r(s_wfc[(fo + t * 8 + lr) * 68 + k0 + lc]));
                bfr[1] = __float_as_uint(tf32r(s_wfc[(fo + t * 8 + lr) * 68 + k0 + lc + 4]));
                mma16n8k8(acc[t], a, bfr);
            }
        }
        float* ob = out + (size_t)b * 4096;
        #pragma unroll
        for (int t = 0; t < 4; t++) {
            const int o = fo + t * 8 + lc * 2;
            redg_add(ob + (fm + lr) * 64 + o,     acc[t][0]);
            redg_add(ob + (fm + lr) * 64 + o + 1, acc[t][1]);
            redg_add(ob + (fm + lr + 8) * 64 + o,     acc[t][2]);
            redg_add(ob + (fm + lr + 8) * 64 + o + 1, acc[t][3]);
        }
    }
}

// ---------------------------------------------------------------------------
extern "C" void kernel_launch(void* const* d_in, const int* in_sizes, int n_in,
                              void* d_out, int out_size) {
    const float* feat  = (const float*)d_in[0];
    const int*   sidx  = (const int*)  d_in[1];
    const float* gamma = (const float*)d_in[2];
    const float* beta  = (const float*)d_in[3];
    const float* Wq    = (const float*)d_in[4];
    const float* Wk    = (const float*)d_in[5];
    const float* Wv1   = (const float*)d_in[6];
    const float* Wv2   = (const float*)d_in[7];
    const float* Wfc   = (const float*)d_in[8];

    float* out  = (float*)d_out;
    float* attn = out + (size_t)Bc * Nc * 64;

    cudaFuncSetAttribute(ln_y_kernel, cudaFuncAttributeMaxDynamicSharedMemorySize, SMEMY);
    cudaFuncSetAttribute(head_mma,    cudaFuncAttributeMaxDynamicSharedMemorySize, SMEM2);

    zero_out<<<2048, 256>>>(out);
    ln_y_kernel<<<Bc, 256, SMEMY>>>(feat, gamma, beta);
    head_mma<<<dim3(Hc, Bc), 256, SMEM2>>>(feat, sidx, Wk, Wv1, Wv2, Wq, Wfc, out, attn);
}